// round 11
// baseline (speedup 1.0000x reference)
#include <cuda_runtime.h>
#include <cuda_fp16.h>
#include <stdint.h>
#include <math.h>

// Fixed shapes for GraphAttentionLayer_18021682774974
#define Bb  32
#define Nn  1024
#define Cc  1024
#define Hh  8
#define Dd  128
#define BHn 256
#define MROWS (Bb * Nn)              // 32768
#define XW  (BHn * Nn * Dd)          // 33.5M

// log-domain shift so P = exp(S - PSHIFT) fits fp16 (S_max ~ 16 << 23.1).
#define PSHIFT 12.0f

// Pre-split half operands + scratch (device globals; no cudaMalloc allowed)
__device__ __half g_hh [MROWS * Cc], g_hl [MROWS * Cc];   // h split
__device__ __half g_Wh [Cc * Cc],    g_Wl [Cc * Cc];      // W split
__device__ __half g_Mth[Dd * Dd],    g_Mtl[Dd * Dd];      // M^T split
__device__ __half g_Xh [XW], g_Xl [XW];                   // X  [z][n][d]
__device__ __half g_XMh[XW];                              // XM hi only
__device__ __half g_VTh[XW], g_VTl[XW];                   // X^T [z][d][n]
__device__ __half g_Ph [(size_t)BHn * Nn * Nn];           // P fp16 (512MB)
__device__ float  g_L  [BHn * Nn * 8];                    // row-sum partials
__device__ float  g_O  [XW];                              // attention out

// ---------------------------------------------------------------------------
__device__ __forceinline__ uint32_t smem_u32(const void* p) {
    uint32_t a;
    asm("{ .reg .u64 t; cvta.to.shared.u64 t, %1; cvt.u32.u64 %0, t; }"
        : "=r"(a) : "l"(p));
    return a;
}
__device__ __forceinline__ void cp16(uint32_t sa, const void* gp) {
    asm volatile("cp.async.cg.shared.global [%0], [%1], 16;" :: "r"(sa), "l"(gp));
}
#define CP_COMMIT() asm volatile("cp.async.commit_group;" ::: "memory")
#define CP_WAIT1()  asm volatile("cp.async.wait_group 1;" ::: "memory")

#define MMA_F16(d, a, b)                                                      \
    asm volatile("mma.sync.aligned.m16n8k16.row.col.f32.f16.f16.f32 "         \
                 "{%0,%1,%2,%3}, {%4,%5,%6,%7}, {%8,%9}, {%0,%1,%2,%3};"      \
                 : "+f"((d)[0]), "+f"((d)[1]), "+f"((d)[2]), "+f"((d)[3])     \
                 : "r"((a)[0]), "r"((a)[1]), "r"((a)[2]), "r"((a)[3]),        \
                   "r"((b)[0]), "r"((b)[1]))

#define LDMX4(r0, r1, r2, r3, a)                                              \
    asm volatile("ldmatrix.sync.aligned.m8n8.x4.shared.b16 {%0,%1,%2,%3}, [%4];" \
                 : "=r"(r0), "=r"(r1), "=r"(r2), "=r"(r3) : "r"(a))

// ---------------------------------------------------------------------------
// Elementwise fp32 -> fp16 hi/lo split (vectorized float4)
// ---------------------------------------------------------------------------
__global__ void __launch_bounds__(256) k_split(const float* __restrict__ src,
                                               __half* __restrict__ hi,
                                               __half* __restrict__ lo, int n4)
{
    int i = blockIdx.x * 256 + threadIdx.x;
    if (i >= n4) return;
    float4 v = ((const float4*)src)[i];
    __half h0 = __float2half_rn(v.x), h1 = __float2half_rn(v.y);
    __half h2 = __float2half_rn(v.z), h3 = __float2half_rn(v.w);
    ((__half2*)hi)[2*i]   = __halves2half2(h0, h1);
    ((__half2*)hi)[2*i+1] = __halves2half2(h2, h3);
    ((__half2*)lo)[2*i]   = __floats2half2_rn(v.x - __half2float(h0),
                                              v.y - __half2float(h1));
    ((__half2*)lo)[2*i+1] = __floats2half2_rn(v.z - __half2float(h2),
                                              v.w - __half2float(h3));
}

// M^T split (tiny, one block)
__global__ void __launch_bounds__(256) k_splitMt(const float* __restrict__ M)
{
    for (int i = threadIdx.x; i < Dd * Dd; i += 256) {
        int e = i >> 7, k = i & 127;
        float v = M[k * Dd + e];
        __half h = __float2half_rn(v);
        g_Mth[i] = h;
        g_Mtl[i] = __float2half_rn(v - __half2float(h));
    }
}

// ===========================================================================
// Unified f16 GEMM, cp.async 3-stage pipeline + ldmatrix fragment loads.
// D[128x128] = A @ B^T. CTA = 128 threads (4 warps, 2x2 of 64x64 warp tiles).
// K-chunk = 32 halfs. 16B chunk (row r, ch of 4) at index (ch ^ ((r>>1)&3)).
// Stage words: modes 0,1: AH[2048] AL[2048] BH[2048] BL[2048] = 8192
//              modes 2,3: AH[2048]          BH[2048] BL[2048] = 6144
// MODE 0: X  = h @ W^T + bias   3-term  K=1024  occ2
// MODE 1: XM = X @ M            3-term  K=128   occ2
// MODE 2: P  = exp(XMh@X^T-12)  2-term  K=128   occ3
// MODE 3: O  = (P @ V) / l      2-term  K=1024  occ3
// ===========================================================================
template<int MODE>
__global__ void __launch_bounds__(128, (MODE >= 2 ? 3 : 2))
k_gemm(const float* __restrict__ bias)
{
    extern __shared__ uint32_t smw[];
    constexpr bool ALO = (MODE <= 1);               // A has a lo plane
    constexpr int  STG = ALO ? 8192 : 6144;         // words per stage
    constexpr int  NC  = (MODE == 0 || MODE == 3) ? 32 : 4;
    constexpr int  BOFF = ALO ? 4096 : 2048;        // B offset in words

    const int tid = threadIdx.x;
    const int wid = tid >> 5, lane = tid & 31;
    const int wm  = wid >> 1, wn = wid & 1;
    const int g   = lane >> 2, t = lane & 3;
    const int lr  = lane & 15, kh = lane >> 4;      // ldmatrix row / k-half
    const uint32_t sbase = smem_u32(smw);

    int m0 = 0, n0 = 0; size_t z = 0;
    const __half *Ah = nullptr, *Al = nullptr, *Bh = nullptr, *Bl = nullptr;
    int Ast = 0, Bst = 0;
    if (MODE == 0) {
        m0 = blockIdx.y * 128; n0 = blockIdx.x * 128;
        Ah = g_hh + (size_t)m0 * Cc;  Al = g_hl + (size_t)m0 * Cc;  Ast = Cc;
        Bh = g_Wh + (size_t)n0 * Cc;  Bl = g_Wl + (size_t)n0 * Cc;  Bst = Cc;
    } else if (MODE == 1) {
        m0 = blockIdx.x * 128;
        Ah = g_Xh + (size_t)m0 * Dd;  Al = g_Xl + (size_t)m0 * Dd;  Ast = Dd;
        Bh = g_Mth;                   Bl = g_Mtl;                   Bst = Dd;
    } else if (MODE == 2) {
        z = blockIdx.z; m0 = blockIdx.y * 128; n0 = blockIdx.x * 128;
        Ah = g_XMh + (z * Nn + m0) * (size_t)Dd;  Ast = Dd;
        Bh = g_Xh  + (z * Nn + n0) * (size_t)Dd;
        Bl = g_Xl  + (z * Nn + n0) * (size_t)Dd;  Bst = Dd;
    } else {
        z = blockIdx.y; m0 = blockIdx.x * 128;
        Ah = g_Ph  + (z * Nn + m0) * (size_t)Nn;  Ast = Nn;
        Bh = g_VTh + z * (size_t)(Dd * Nn);
        Bl = g_VTl + z * (size_t)(Dd * Nn);       Bst = Nn;
    }

    float acc[4][8][4];
    #pragma unroll
    for (int a = 0; a < 4; ++a)
        #pragma unroll
        for (int b = 0; b < 8; ++b)
            #pragma unroll
            for (int c = 0; c < 4; ++c) acc[a][b][c] = 0.f;

    auto load_stage = [&](int st, int k0) {
        const uint32_t sb = sbase + (uint32_t)st * STG * 4;
        #pragma unroll
        for (int i = 0; i < 4; ++i) {                       // A: 128r x 4 chunks
            int idx = tid + (i << 7);
            int r = idx >> 2, ch = idx & 3;
            uint32_t d = sb + (uint32_t)(r * 64 + ((ch ^ ((r >> 1) & 3)) << 4));
            const size_t go = (size_t)r * Ast + k0 + ch * 8;
            cp16(d, Ah + go);
            if (ALO) cp16(d + 2048 * 4, Al + go);
        }
        #pragma unroll
        for (int i = 0; i < 4; ++i) {                       // B: 128r x 4 chunks
            int idx = tid + (i << 7);
            int r = idx >> 2, ch = idx & 3;
            uint32_t d = sb + (uint32_t)(BOFF * 4)
                       + (uint32_t)(r * 64 + ((ch ^ ((r >> 1) & 3)) << 4));
            const size_t go = (size_t)r * Bst + k0 + ch * 8;
            cp16(d, Bh + go);
            cp16(d + 2048 * 4, Bl + go);
        }
    };

    // prologue
    load_stage(0, 0);  CP_COMMIT();
    load_stage(1, 32); CP_COMMIT();

    for (int c = 0; c < NC; ++c) {
        CP_WAIT1();
        __syncthreads();
        if (c + 2 < NC) load_stage((c + 2) % 3, (c + 2) * 32);
        CP_COMMIT();

        const uint32_t stb = sbase + (uint32_t)((c % 3) * STG) * 4;
        const uint32_t aHb = stb;
        const uint32_t aLb = stb + 2048 * 4;
        const uint32_t bHb = stb + BOFF * 4;
        const uint32_t bLb = bHb + 2048 * 4;

        #pragma unroll
        for (int ks = 0; ks < 2; ++ks) {
            const int cI = 2 * ks + kh;                      // 16B chunk index
            // per-lane ldmatrix row offsets (row, chunk) with swizzle
            uint32_t aoff[4], boff[4];
            #pragma unroll
            for (int mf = 0; mf < 4; ++mf) {
                int r = wm * 64 + mf * 16 + lr;
                aoff[mf] = (uint32_t)(r * 64 + ((cI ^ ((r >> 1) & 3)) << 4));
            }
            #pragma unroll
            for (int p = 0; p < 4; ++p) {
                int r = wn * 64 + p * 16 + lr;
                boff[p] = (uint32_t)(r * 64 + ((cI ^ ((r >> 1) & 3)) << 4));
            }

            uint32_t ah[4][4], bb[8][2];
            #pragma unroll
            for (int mf = 0; mf < 4; ++mf)
                LDMX4(ah[mf][0], ah[mf][1], ah[mf][2], ah[mf][3], aHb + aoff[mf]);
            #pragma unroll
            for (int p = 0; p < 4; ++p) {
                uint32_t q0, q1, q2, q3;
                LDMX4(q0, q1, q2, q3, bHb + boff[p]);
                bb[2*p][0]   = q0; bb[2*p][1]   = q2;
                bb[2*p+1][0] = q1; bb[2*p+1][1] = q3;
            }
            // term 1: A_hi x B_hi
            #pragma unroll
            for (int mf = 0; mf < 4; ++mf)
                #pragma unroll
                for (int nf = 0; nf < 8; ++nf)
                    MMA_F16(acc[mf][nf], ah[mf], bb[nf]);
            // term (3-term modes): A_lo x B_hi   (B_hi still live)
            if (ALO) {
                uint32_t al[4][4];
                #pragma unroll
                for (int mf = 0; mf < 4; ++mf)
                    LDMX4(al[mf][0], al[mf][1], al[mf][2], al[mf][3], aLb + aoff[mf]);
                #pragma unroll
                for (int mf = 0; mf < 4; ++mf)
                    #pragma unroll
                    for (int nf = 0; nf < 8; ++nf)
                        MMA_F16(acc[mf][nf], al[mf], bb[nf]);
            }
            // term 2: A_hi x B_lo
            #pragma unroll
            for (int p = 0; p < 4; ++p) {
                uint32_t q0, q1, q2, q3;
                LDMX4(q0, q1, q2, q3, bLb + boff[p]);
                bb[2*p][0]   = q0; bb[2*p][1]   = q2;
                bb[2*p+1][0] = q1; bb[2*p+1][1] = q3;
            }
            #pragma unroll
            for (int mf = 0; mf < 4; ++mf)
                #pragma unroll
                for (int nf = 0; nf < 8; ++nf)
                    MMA_F16(acc[mf][nf], ah[mf], bb[nf]);
        }
    }
    __syncthreads();

    // ---- epilogue ----
    if (MODE == 0) {
        const int head = blockIdx.x;
        #pragma unroll
        for (int mf = 0; mf < 4; ++mf)
            #pragma unroll
            for (int hh = 0; hh < 2; ++hh) {
                int m = m0 + wm * 64 + mf * 16 + g + 8 * hh;
                int bidx = m >> 10, tok = m & 1023;
                size_t ro = (((size_t)bidx * Hh + head) * Nn + tok) * Dd;
                #pragma unroll
                for (int nf = 0; nf < 8; ++nf) {
                    int col = wn * 64 + nf * 8 + 2 * t;
                    float v0 = acc[mf][nf][2*hh+0] + bias[n0 + col];
                    float v1 = acc[mf][nf][2*hh+1] + bias[n0 + col + 1];
                    __half h0 = __float2half_rn(v0), h1 = __float2half_rn(v1);
                    *(__half2*)(g_Xh + ro + col) = __halves2half2(h0, h1);
                    *(__half2*)(g_Xl + ro + col) =
                        __floats2half2_rn(v0 - __half2float(h0),
                                          v1 - __half2float(h1));
                }
            }
    } else if (MODE == 1) {
        #pragma unroll
        for (int mf = 0; mf < 4; ++mf)
            #pragma unroll
            for (int hh = 0; hh < 2; ++hh) {
                size_t ro = (size_t)(m0 + wm * 64 + mf * 16 + g + 8 * hh) * Dd;
                #pragma unroll
                for (int nf = 0; nf < 8; ++nf) {
                    int col = wn * 64 + nf * 8 + 2 * t;
                    __half h0 = __float2half_rn(acc[mf][nf][2*hh+0]);
                    __half h1 = __float2half_rn(acc[mf][nf][2*hh+1]);
                    *(__half2*)(g_XMh + ro + col) = __halves2half2(h0, h1);
                }
            }
    } else if (MODE == 2) {
        float rsum[4][2];
        #pragma unroll
        for (int mf = 0; mf < 4; ++mf) { rsum[mf][0] = 0.f; rsum[mf][1] = 0.f; }
        #pragma unroll
        for (int mf = 0; mf < 4; ++mf)
            #pragma unroll
            for (int hh = 0; hh < 2; ++hh) {
                int rm = wm * 64 + mf * 16 + g + 8 * hh;
                __half* dst = g_Ph + (z * Nn + m0 + rm) * (size_t)Nn + n0;
                #pragma unroll
                for (int nf = 0; nf < 8; ++nf) {
                    int col = wn * 64 + nf * 8 + 2 * t;
                    __half p0 = __float2half_rn(__expf(acc[mf][nf][2*hh+0] - PSHIFT));
                    __half p1 = __float2half_rn(__expf(acc[mf][nf][2*hh+1] - PSHIFT));
                    rsum[mf][hh] += __half2float(p0) + __half2float(p1);
                    *(__half2*)(dst + col) = __halves2half2(p0, p1);
                }
            }
        float* ssum = (float*)smw;   // alias stage smem (compute done)
        #pragma unroll
        for (int mf = 0; mf < 4; ++mf)
            #pragma unroll
            for (int hh = 0; hh < 2; ++hh) {
                float s = rsum[mf][hh];
                s += __shfl_xor_sync(0xffffffffu, s, 1);
                s += __shfl_xor_sync(0xffffffffu, s, 2);
                if (t == 0)
                    ssum[(wm * 64 + mf * 16 + g + 8 * hh) * 2 + wn] = s;
            }
        __syncthreads();
        {
            float l = ssum[tid * 2] + ssum[tid * 2 + 1];
            g_L[(z * Nn + m0 + tid) * 8 + blockIdx.x] = l;
        }
    } else {  // MODE 3 (PV)
        #pragma unroll
        for (int mf = 0; mf < 4; ++mf)
            #pragma unroll
            for (int hh = 0; hh < 2; ++hh) {
                size_t row = z * Nn + m0 + wm * 64 + mf * 16 + g + 8 * hh;
                const float* lp = g_L + row * 8;
                float l = ((lp[0] + lp[1]) + (lp[2] + lp[3]))
                        + ((lp[4] + lp[5]) + (lp[6] + lp[7]));
                float inv = 1.f / l;
                float* dst = g_O + row * (size_t)Dd;
                #pragma unroll
                for (int nf = 0; nf < 8; ++nf) {
                    int col = wn * 64 + nf * 8 + 2 * t;
                    *(float2*)(dst + col) =
                        make_float2(acc[mf][nf][2*hh+0] * inv,
                                    acc[mf][nf][2*hh+1] * inv);
                }
            }
    }
}

// ---------------------------------------------------------------------------
// Transpose X_hi/X_lo -> VT_hi/VT_lo  ([z][n][d] -> [z][d][n])
// ---------------------------------------------------------------------------
__global__ void __launch_bounds__(256) k_transpose()
{
    __shared__ __half th[32][33], tl[32][33];
    const int z  = blockIdx.z;
    const int d0 = blockIdx.y << 5;
    const int nb = blockIdx.x << 5;
    const int lx = threadIdx.x, ly = threadIdx.y;
    const __half* sh = g_Xh + (size_t)z * Nn * Dd;
    const __half* sl = g_Xl + (size_t)z * Nn * Dd;
    #pragma unroll
    for (int i = 0; i < 32; i += 8) {
        th[ly + i][lx] = sh[(size_t)(nb + ly + i) * Dd + d0 + lx];
        tl[ly + i][lx] = sl[(size_t)(nb + ly + i) * Dd + d0 + lx];
    }
    __syncthreads();
    __half* dh = g_VTh + (size_t)z * Dd * Nn;
    __half* dl = g_VTl + (size_t)z * Dd * Nn;
    #pragma unroll
    for (int i = 0; i < 32; i += 8) {
        dh[(size_t)(d0 + ly + i) * Nn + nb + lx] = th[lx][ly + i];
        dl[(size_t)(d0 + ly + i) * Nn + nb + lx] = tl[lx][ly + i];
    }
}

// ---------------------------------------------------------------------------
// LayerNorm + exact GELU over c (gather heads)
// ---------------------------------------------------------------------------
__global__ void __launch_bounds__(256) k_ln_gelu(const float* __restrict__ gamma,
                                                 const float* __restrict__ beta,
                                                 float* __restrict__ out)
{
    const int row = blockIdx.x;
    const int bbi = row >> 10, nn = row & 1023;
    const int tid = threadIdx.x;
    const int c0 = tid * 4, head = c0 >> 7, dd = c0 & 127;

    const float* src = g_O + (((size_t)bbi * Hh + head) * Nn + nn) * Dd + dd;
    float4 v = *(const float4*)src;

    float s = v.x + v.y + v.z + v.w;
    float q = v.x*v.x + v.y*v.y + v.z*v.z + v.w*v.w;
    #pragma unroll
    for (int off = 16; off >= 1; off >>= 1) {
        s += __shfl_xor_sync(0xffffffffu, s, off);
        q += __shfl_xor_sync(0xffffffffu, q, off);
    }
    __shared__ float ss[8], sq[8];
    if ((tid & 31) == 0) { ss[tid >> 5] = s; sq[tid >> 5] = q; }
    __syncthreads();
    float st = 0.f, qt = 0.f;
    #pragma unroll
    for (int k = 0; k < 8; ++k) { st += ss[k]; qt += sq[k]; }

    const float mean = st * (1.f / (float)Cc);
    const float var  = qt * (1.f / (float)Cc) - mean * mean;
    const float rstd = rsqrtf(var + 1e-5f);

    float4 gm = *(const float4*)(gamma + c0);
    float4 be = *(const float4*)(beta + c0);
    float y0 = (v.x - mean) * rstd * gm.x + be.x;
    float y1 = (v.y - mean) * rstd * gm.y + be.y;
    float y2 = (v.z - mean) * rstd * gm.z + be.z;
    float y3 = (v.w - mean) * rstd * gm.w + be.w;

    const float k2 = 0.70710678118654752440f;
    float4 rr;
    rr.x = 0.5f * y0 * (1.f + erff(y0 * k2));
    rr.y = 0.5f * y1 * (1.f + erff(y1 * k2));
    rr.z = 0.5f * y2 * (1.f + erff(y2 * k2));
    rr.w = 0.5f * y3 * (1.f + erff(y3 * k2));
    *(float4*)(out + (size_t)row * Cc + c0) = rr;
}

// ---------------------------------------------------------------------------
#define SMEM_3T (3 * 8192 * 4)    // 98304 B  (modes 0,1)
#define SMEM_2T (3 * 6144 * 4)    // 73728 B  (modes 2,3)

extern "C" void kernel_launch(void* const* d_in, const int* in_sizes, int n_in,
                              void* d_out, int out_size)
{
    const float* h     = (const float*)d_in[0];
    const float* W_w   = (const float*)d_in[1];
    const float* W_b   = (const float*)d_in[2];
    const float* Mmat  = (const float*)d_in[3];
    const float* gamma = (const float*)d_in[4];
    const float* beta  = (const float*)d_in[5];
    float* out = (float*)d_out;

    cudaFuncSetAttribute(k_gemm<0>, cudaFuncAttributeMaxDynamicSharedMemorySize, SMEM_3T);
    cudaFuncSetAttribute(k_gemm<1>, cudaFuncAttributeMaxDynamicSharedMemorySize, SMEM_3T);
    cudaFuncSetAttribute(k_gemm<2>, cudaFuncAttributeMaxDynamicSharedMemorySize, SMEM_2T);
    cudaFuncSetAttribute(k_gemm<3>, cudaFuncAttributeMaxDynamicSharedMemorySize, SMEM_2T);

    __half *hh, *hl, *wh, *wl;
    cudaGetSymbolAddress((void**)&hh, g_hh);
    cudaGetSymbolAddress((void**)&hl, g_hl);
    cudaGetSymbolAddress((void**)&wh, g_Wh);
    cudaGetSymbolAddress((void**)&wl, g_Wl);

    // 0) pre-split inputs
    k_split<<<(MROWS * Cc / 4) / 256, 256>>>(h,   hh, hl, MROWS * Cc / 4);
    k_split<<<(Cc * Cc / 4) / 256,    256>>>(W_w, wh, wl, Cc * Cc / 4);
    k_splitMt<<<1, 256>>>(Mmat);

    // 1) X = h @ W^T + b          -> X_hi/X_lo          (3-term f16)
    k_gemm<0><<<dim3(Hh, MROWS / 128), 128, SMEM_3T>>>(W_b);
    // 2) X^T                      -> VT_hi/VT_lo
    k_transpose<<<dim3(Nn / 32, Dd / 32, BHn), dim3(32, 8)>>>();
    // 3) XM = X @ M               -> XM_hi               (3-term f16)
    k_gemm<1><<<dim3((BHn * Nn) / 128), 128, SMEM_3T>>>(nullptr);
    // 4) P = exp(S - 12), lpart   -> g_Ph (fp16), g_L    (2-term f16)
    k_gemm<2><<<dim3(Nn / 128, Nn / 128, BHn), 128, SMEM_2T>>>(nullptr);
    // 5) O = (P @ V) / l          -> g_O                 (2-term f16)
    k_gemm<3><<<dim3(Nn / 128, BHn), 128, SMEM_2T>>>(nullptr);
    // 6) LayerNorm + GELU         -> out
    k_ln_gelu<<<MROWS, 256>>>(gamma, beta, out);
}

// round 12
// speedup vs baseline: 1.0364x; 1.0364x over previous
#include <cuda_runtime.h>
#include <cuda_fp16.h>
#include <stdint.h>
#include <math.h>

// Fixed shapes for GraphAttentionLayer_18021682774974
#define Bb  32
#define Nn  1024
#define Cc  1024
#define Hh  8
#define Dd  128
#define BHn 256
#define MROWS (Bb * Nn)              // 32768
#define XW  (BHn * Nn * Dd)          // 33.5M

// log-domain shift so P = exp(S - PSHIFT) fits fp16 (S_max ~ 16 << 23.1).
#define PSHIFT 12.0f

// Pre-split half operands + scratch (device globals; no cudaMalloc allowed)
__device__ __half g_hh [MROWS * Cc], g_hl [MROWS * Cc];   // h split
__device__ __half g_Wh [Cc * Cc],    g_Wl [Cc * Cc];      // W split
__device__ __half g_Mth[Dd * Dd],    g_Mtl[Dd * Dd];      // M^T split
__device__ __half g_Xh [XW], g_Xl [XW];                   // X  [z][n][d]
__device__ __half g_XMh[XW];                              // XM hi only
__device__ __half g_VTh[XW], g_VTl[XW];                   // X^T [z][d][n]
__device__ __half g_Ph [(size_t)BHn * Nn * Nn];           // P fp16 (512MB)
__device__ float  g_L  [BHn * Nn * 8];                    // row-sum partials
__device__ float  g_O  [XW];                              // attention out

// ---------------------------------------------------------------------------
__device__ __forceinline__ uint32_t smem_u32(const void* p) {
    uint32_t a;
    asm("{ .reg .u64 t; cvta.to.shared.u64 t, %1; cvt.u32.u64 %0, t; }"
        : "=r"(a) : "l"(p));
    return a;
}
__device__ __forceinline__ void cp16(uint32_t sa, const void* gp) {
    asm volatile("cp.async.cg.shared.global [%0], [%1], 16;" :: "r"(sa), "l"(gp));
}
#define CP_COMMIT() asm volatile("cp.async.commit_group;" ::: "memory")
#define CP_WAIT1()  asm volatile("cp.async.wait_group 1;" ::: "memory")

#define MMA_F16(d, a, b)                                                      \
    asm volatile("mma.sync.aligned.m16n8k16.row.col.f32.f16.f16.f32 "         \
                 "{%0,%1,%2,%3}, {%4,%5,%6,%7}, {%8,%9}, {%0,%1,%2,%3};"      \
                 : "+f"((d)[0]), "+f"((d)[1]), "+f"((d)[2]), "+f"((d)[3])     \
                 : "r"((a)[0]), "r"((a)[1]), "r"((a)[2]), "r"((a)[3]),        \
                   "r"((b)[0]), "r"((b)[1]))

#define LDMX4(r0, r1, r2, r3, a)                                              \
    asm volatile("ldmatrix.sync.aligned.m8n8.x4.shared.b16 {%0,%1,%2,%3}, [%4];" \
                 : "=r"(r0), "=r"(r1), "=r"(r2), "=r"(r3) : "r"(a))

// ---------------------------------------------------------------------------
// Elementwise fp32 -> fp16 hi/lo split (vectorized float4)
// ---------------------------------------------------------------------------
__global__ void __launch_bounds__(256) k_split(const float* __restrict__ src,
                                               __half* __restrict__ hi,
                                               __half* __restrict__ lo, int n4)
{
    int i = blockIdx.x * 256 + threadIdx.x;
    if (i >= n4) return;
    float4 v = ((const float4*)src)[i];
    __half h0 = __float2half_rn(v.x), h1 = __float2half_rn(v.y);
    __half h2 = __float2half_rn(v.z), h3 = __float2half_rn(v.w);
    ((__half2*)hi)[2*i]   = __halves2half2(h0, h1);
    ((__half2*)hi)[2*i+1] = __halves2half2(h2, h3);
    ((__half2*)lo)[2*i]   = __floats2half2_rn(v.x - __half2float(h0),
                                              v.y - __half2float(h1));
    ((__half2*)lo)[2*i+1] = __floats2half2_rn(v.z - __half2float(h2),
                                              v.w - __half2float(h3));
}

// M^T split (tiny, one block)
__global__ void __launch_bounds__(256) k_splitMt(const float* __restrict__ M)
{
    for (int i = threadIdx.x; i < Dd * Dd; i += 256) {
        int e = i >> 7, k = i & 127;
        float v = M[k * Dd + e];
        __half h = __float2half_rn(v);
        g_Mth[i] = h;
        g_Mtl[i] = __float2half_rn(v - __half2float(h));
    }
}

// ===========================================================================
// Unified f16 GEMM, cp.async 3-stage pipeline + ldmatrix with HOISTED offsets.
// D[128x128] = A @ B^T. CTA = 128 threads (4 warps, 2x2 of 64x64 warp tiles),
// 2 CTAs/SM everywhere. K-chunk = 32 halfs.
// 16B chunk (row r, ch of 4) at chunk index (ch ^ ((r>>1)&3)).
// Stage words: modes 0,1: AH[2048] AL[2048] BH[2048] BL[2048] = 8192
//              modes 2,3: AH[2048]          BH[2048] BL[2048] = 6144
// MODE 0: X  = h @ W^T + bias   3-term  K=1024
// MODE 1: XM = X @ M            3-term  K=128
// MODE 2: P  = exp(XMh@X^T-12)  2-term  K=128
// MODE 3: O  = (P @ V) / l      2-term  K=1024
// ===========================================================================
template<int MODE>
__global__ void __launch_bounds__(128, 2) k_gemm(const float* __restrict__ bias)
{
    extern __shared__ uint32_t smw[];
    constexpr bool ALO = (MODE <= 1);               // A has a lo plane
    constexpr int  STG = ALO ? 8192 : 6144;         // words per stage
    constexpr int  NC  = (MODE == 0 || MODE == 3) ? 32 : 4;
    constexpr int  BOFF = ALO ? 4096 : 2048;        // B offset in words

    const int tid = threadIdx.x;
    const int wid = tid >> 5, lane = tid & 31;
    const int wm  = wid >> 1, wn = wid & 1;
    const int g   = lane >> 2, t = lane & 3;
    const int lr  = lane & 15, kh = lane >> 4;      // ldmatrix row / k-half
    const uint32_t sbase = smem_u32(smw);

    int m0 = 0, n0 = 0; size_t z = 0;
    const __half *Ah = nullptr, *Al = nullptr, *Bh = nullptr, *Bl = nullptr;
    int Ast = 0, Bst = 0;
    if (MODE == 0) {
        m0 = blockIdx.y * 128; n0 = blockIdx.x * 128;
        Ah = g_hh + (size_t)m0 * Cc;  Al = g_hl + (size_t)m0 * Cc;  Ast = Cc;
        Bh = g_Wh + (size_t)n0 * Cc;  Bl = g_Wl + (size_t)n0 * Cc;  Bst = Cc;
    } else if (MODE == 1) {
        m0 = blockIdx.x * 128;
        Ah = g_Xh + (size_t)m0 * Dd;  Al = g_Xl + (size_t)m0 * Dd;  Ast = Dd;
        Bh = g_Mth;                   Bl = g_Mtl;                   Bst = Dd;
    } else if (MODE == 2) {
        z = blockIdx.z; m0 = blockIdx.y * 128; n0 = blockIdx.x * 128;
        Ah = g_XMh + (z * Nn + m0) * (size_t)Dd;  Ast = Dd;
        Bh = g_Xh  + (z * Nn + n0) * (size_t)Dd;
        Bl = g_Xl  + (z * Nn + n0) * (size_t)Dd;  Bst = Dd;
    } else {
        z = blockIdx.y; m0 = blockIdx.x * 128;
        Ah = g_Ph  + (z * Nn + m0) * (size_t)Nn;  Ast = Nn;
        Bh = g_VTh + z * (size_t)(Dd * Nn);
        Bl = g_VTl + z * (size_t)(Dd * Nn);       Bst = Nn;
    }

    float acc[4][8][4];
    #pragma unroll
    for (int a = 0; a < 4; ++a)
        #pragma unroll
        for (int b = 0; b < 8; ++b)
            #pragma unroll
            for (int c = 0; c < 4; ++c) acc[a][b][c] = 0.f;

    // HOISTED per-lane swizzled ldmatrix byte offsets (c-invariant).
    uint32_t aoffs[2][4], boffs[2][4];
    #pragma unroll
    for (int ks = 0; ks < 2; ++ks) {
        const int cI = 2 * ks + kh;
        #pragma unroll
        for (int mf = 0; mf < 4; ++mf) {
            int r = wm * 64 + mf * 16 + lr;
            aoffs[ks][mf] = (uint32_t)(r * 64 + ((cI ^ ((r >> 1) & 3)) << 4));
        }
        #pragma unroll
        for (int p = 0; p < 4; ++p) {
            int r = wn * 64 + p * 16 + lr;
            boffs[ks][p] = (uint32_t)(r * 64 + ((cI ^ ((r >> 1) & 3)) << 4));
        }
    }

    auto load_stage = [&](int st, int k0) {
        const uint32_t sb = sbase + (uint32_t)st * STG * 4;
        #pragma unroll
        for (int i = 0; i < 4; ++i) {                       // A: 128r x 4 chunks
            int idx = tid + (i << 7);
            int r = idx >> 2, ch = idx & 3;
            uint32_t d = sb + (uint32_t)(r * 64 + ((ch ^ ((r >> 1) & 3)) << 4));
            const size_t go = (size_t)r * Ast + k0 + ch * 8;
            cp16(d, Ah + go);
            if (ALO) cp16(d + 2048 * 4, Al + go);
        }
        #pragma unroll
        for (int i = 0; i < 4; ++i) {                       // B: 128r x 4 chunks
            int idx = tid + (i << 7);
            int r = idx >> 2, ch = idx & 3;
            uint32_t d = sb + (uint32_t)(BOFF * 4)
                       + (uint32_t)(r * 64 + ((ch ^ ((r >> 1) & 3)) << 4));
            const size_t go = (size_t)r * Bst + k0 + ch * 8;
            cp16(d, Bh + go);
            cp16(d + 2048 * 4, Bl + go);
        }
    };

    // prologue
    load_stage(0, 0);  CP_COMMIT();
    load_stage(1, 32); CP_COMMIT();

    for (int c = 0; c < NC; ++c) {
        CP_WAIT1();
        __syncthreads();
        if (c + 2 < NC) load_stage((c + 2) % 3, (c + 2) * 32);
        CP_COMMIT();

        const uint32_t stb = sbase + (uint32_t)((c % 3) * STG) * 4;
        const uint32_t aHb = stb;
        const uint32_t aLb = stb + 2048 * 4;
        const uint32_t bHb = stb + BOFF * 4;
        const uint32_t bLb = bHb + 2048 * 4;

        #pragma unroll
        for (int ks = 0; ks < 2; ++ks) {
            uint32_t ah[4][4], bb[8][2];
            #pragma unroll
            for (int mf = 0; mf < 4; ++mf)
                LDMX4(ah[mf][0], ah[mf][1], ah[mf][2], ah[mf][3],
                      aHb + aoffs[ks][mf]);
            #pragma unroll
            for (int p = 0; p < 4; ++p) {
                uint32_t q0, q1, q2, q3;
                LDMX4(q0, q1, q2, q3, bHb + boffs[ks][p]);
                bb[2*p][0]   = q0; bb[2*p][1]   = q2;
                bb[2*p+1][0] = q1; bb[2*p+1][1] = q3;
            }
            // term 1: A_hi x B_hi
            #pragma unroll
            for (int mf = 0; mf < 4; ++mf)
                #pragma unroll
                for (int nf = 0; nf < 8; ++nf)
                    MMA_F16(acc[mf][nf], ah[mf], bb[nf]);
            // term (3-term modes): A_lo x B_hi   (B_hi still live)
            if (ALO) {
                uint32_t al[4][4];
                #pragma unroll
                for (int mf = 0; mf < 4; ++mf)
                    LDMX4(al[mf][0], al[mf][1], al[mf][2], al[mf][3],
                          aLb + aoffs[ks][mf]);
                #pragma unroll
                for (int mf = 0; mf < 4; ++mf)
                    #pragma unroll
                    for (int nf = 0; nf < 8; ++nf)
                        MMA_F16(acc[mf][nf], al[mf], bb[nf]);
            }
            // term 2: A_hi x B_lo
            #pragma unroll
            for (int p = 0; p < 4; ++p) {
                uint32_t q0, q1, q2, q3;
                LDMX4(q0, q1, q2, q3, bLb + boffs[ks][p]);
                bb[2*p][0]   = q0; bb[2*p][1]   = q2;
                bb[2*p+1][0] = q1; bb[2*p+1][1] = q3;
            }
            #pragma unroll
            for (int mf = 0; mf < 4; ++mf)
                #pragma unroll
                for (int nf = 0; nf < 8; ++nf)
                    MMA_F16(acc[mf][nf], ah[mf], bb[nf]);
        }
    }
    __syncthreads();

    // ---- epilogue ----
    if (MODE == 0) {
        const int head = blockIdx.x;
        #pragma unroll
        for (int mf = 0; mf < 4; ++mf)
            #pragma unroll
            for (int hh = 0; hh < 2; ++hh) {
                int m = m0 + wm * 64 + mf * 16 + g + 8 * hh;
                int bidx = m >> 10, tok = m & 1023;
                size_t ro = (((size_t)bidx * Hh + head) * Nn + tok) * Dd;
                #pragma unroll
                for (int nf = 0; nf < 8; ++nf) {
                    int col = wn * 64 + nf * 8 + 2 * t;
                    float v0 = acc[mf][nf][2*hh+0] + bias[n0 + col];
                    float v1 = acc[mf][nf][2*hh+1] + bias[n0 + col + 1];
                    __half h0 = __float2half_rn(v0), h1 = __float2half_rn(v1);
                    *(__half2*)(g_Xh + ro + col) = __halves2half2(h0, h1);
                    *(__half2*)(g_Xl + ro + col) =
                        __floats2half2_rn(v0 - __half2float(h0),
                                          v1 - __half2float(h1));
                }
            }
    } else if (MODE == 1) {
        #pragma unroll
        for (int mf = 0; mf < 4; ++mf)
            #pragma unroll
            for (int hh = 0; hh < 2; ++hh) {
                size_t ro = (size_t)(m0 + wm * 64 + mf * 16 + g + 8 * hh) * Dd;
                #pragma unroll
                for (int nf = 0; nf < 8; ++nf) {
                    int col = wn * 64 + nf * 8 + 2 * t;
                    __half h0 = __float2half_rn(acc[mf][nf][2*hh+0]);
                    __half h1 = __float2half_rn(acc[mf][nf][2*hh+1]);
                    *(__half2*)(g_XMh + ro + col) = __halves2half2(h0, h1);
                }
            }
    } else if (MODE == 2) {
        float rsum[4][2];
        #pragma unroll
        for (int mf = 0; mf < 4; ++mf) { rsum[mf][0] = 0.f; rsum[mf][1] = 0.f; }
        #pragma unroll
        for (int mf = 0; mf < 4; ++mf)
            #pragma unroll
            for (int hh = 0; hh < 2; ++hh) {
                int rm = wm * 64 + mf * 16 + g + 8 * hh;
                __half* dst = g_Ph + (z * Nn + m0 + rm) * (size_t)Nn + n0;
                #pragma unroll
                for (int nf = 0; nf < 8; ++nf) {
                    int col = wn * 64 + nf * 8 + 2 * t;
                    __half p0 = __float2half_rn(__expf(acc[mf][nf][2*hh+0] - PSHIFT));
                    __half p1 = __float2half_rn(__expf(acc[mf][nf][2*hh+1] - PSHIFT));
                    rsum[mf][hh] += __half2float(p0) + __half2float(p1);
                    *(__half2*)(dst + col) = __halves2half2(p0, p1);
                }
            }
        float* ssum = (float*)smw;   // alias stage smem (compute done)
        #pragma unroll
        for (int mf = 0; mf < 4; ++mf)
            #pragma unroll
            for (int hh = 0; hh < 2; ++hh) {
                float s = rsum[mf][hh];
                s += __shfl_xor_sync(0xffffffffu, s, 1);
                s += __shfl_xor_sync(0xffffffffu, s, 2);
                if (t == 0)
                    ssum[(wm * 64 + mf * 16 + g + 8 * hh) * 2 + wn] = s;
            }
        __syncthreads();
        {
            float l = ssum[tid * 2] + ssum[tid * 2 + 1];
            g_L[(z * Nn + m0 + tid) * 8 + blockIdx.x] = l;
        }
    } else {  // MODE 3 (PV)
        #pragma unroll
        for (int mf = 0; mf < 4; ++mf)
            #pragma unroll
            for (int hh = 0; hh < 2; ++hh) {
                size_t row = z * Nn + m0 + wm * 64 + mf * 16 + g + 8 * hh;
                const float* lp = g_L + row * 8;
                float l = ((lp[0] + lp[1]) + (lp[2] + lp[3]))
                        + ((lp[4] + lp[5]) + (lp[6] + lp[7]));
                float inv = 1.f / l;
                float* dst = g_O + row * (size_t)Dd;
                #pragma unroll
                for (int nf = 0; nf < 8; ++nf) {
                    int col = wn * 64 + nf * 8 + 2 * t;
                    *(float2*)(dst + col) =
                        make_float2(acc[mf][nf][2*hh+0] * inv,
                                    acc[mf][nf][2*hh+1] * inv);
                }
            }
    }
}

// ---------------------------------------------------------------------------
// Transpose X_hi/X_lo -> VT_hi/VT_lo  ([z][n][d] -> [z][d][n])
// ---------------------------------------------------------------------------
__global__ void __launch_bounds__(256) k_transpose()
{
    __shared__ __half th[32][33], tl[32][33];
    const int z  = blockIdx.z;
    const int d0 = blockIdx.y << 5;
    const int nb = blockIdx.x << 5;
    const int lx = threadIdx.x, ly = threadIdx.y;
    const __half* sh = g_Xh + (size_t)z * Nn * Dd;
    const __half* sl = g_Xl + (size_t)z * Nn * Dd;
    #pragma unroll
    for (int i = 0; i < 32; i += 8) {
        th[ly + i][lx] = sh[(size_t)(nb + ly + i) * Dd + d0 + lx];
        tl[ly + i][lx] = sl[(size_t)(nb + ly + i) * Dd + d0 + lx];
    }
    __syncthreads();
    __half* dh = g_VTh + (size_t)z * Dd * Nn;
    __half* dl = g_VTl + (size_t)z * Dd * Nn;
    #pragma unroll
    for (int i = 0; i < 32; i += 8) {
        dh[(size_t)(d0 + ly + i) * Nn + nb + lx] = th[lx][ly + i];
        dl[(size_t)(d0 + ly + i) * Nn + nb + lx] = tl[lx][ly + i];
    }
}

// ---------------------------------------------------------------------------
// LayerNorm + exact GELU over c (gather heads)
// ---------------------------------------------------------------------------
__global__ void __launch_bounds__(256) k_ln_gelu(const float* __restrict__ gamma,
                                                 const float* __restrict__ beta,
                                                 float* __restrict__ out)
{
    const int row = blockIdx.x;
    const int bbi = row >> 10, nn = row & 1023;
    const int tid = threadIdx.x;
    const int c0 = tid * 4, head = c0 >> 7, dd = c0 & 127;

    const float* src = g_O + (((size_t)bbi * Hh + head) * Nn + nn) * Dd + dd;
    float4 v = *(const float4*)src;

    float s = v.x + v.y + v.z + v.w;
    float q = v.x*v.x + v.y*v.y + v.z*v.z + v.w*v.w;
    #pragma unroll
    for (int off = 16; off >= 1; off >>= 1) {
        s += __shfl_xor_sync(0xffffffffu, s, off);
        q += __shfl_xor_sync(0xffffffffu, q, off);
    }
    __shared__ float ss[8], sq[8];
    if ((tid & 31) == 0) { ss[tid >> 5] = s; sq[tid >> 5] = q; }
    __syncthreads();
    float st = 0.f, qt = 0.f;
    #pragma unroll
    for (int k = 0; k < 8; ++k) { st += ss[k]; qt += sq[k]; }

    const float mean = st * (1.f / (float)Cc);
    const float var  = qt * (1.f / (float)Cc) - mean * mean;
    const float rstd = rsqrtf(var + 1e-5f);

    float4 gm = *(const float4*)(gamma + c0);
    float4 be = *(const float4*)(beta + c0);
    float y0 = (v.x - mean) * rstd * gm.x + be.x;
    float y1 = (v.y - mean) * rstd * gm.y + be.y;
    float y2 = (v.z - mean) * rstd * gm.z + be.z;
    float y3 = (v.w - mean) * rstd * gm.w + be.w;

    const float k2 = 0.70710678118654752440f;
    float4 rr;
    rr.x = 0.5f * y0 * (1.f + erff(y0 * k2));
    rr.y = 0.5f * y1 * (1.f + erff(y1 * k2));
    rr.z = 0.5f * y2 * (1.f + erff(y2 * k2));
    rr.w = 0.5f * y3 * (1.f + erff(y3 * k2));
    *(float4*)(out + (size_t)row * Cc + c0) = rr;
}

// ---------------------------------------------------------------------------
#define SMEM_3T (3 * 8192 * 4)    // 98304 B  (modes 0,1)
#define SMEM_2T (3 * 6144 * 4)    // 73728 B  (modes 2,3)

extern "C" void kernel_launch(void* const* d_in, const int* in_sizes, int n_in,
                              void* d_out, int out_size)
{
    const float* h     = (const float*)d_in[0];
    const float* W_w   = (const float*)d_in[1];
    const float* W_b   = (const float*)d_in[2];
    const float* Mmat  = (const float*)d_in[3];
    const float* gamma = (const float*)d_in[4];
    const float* beta  = (const float*)d_in[5];
    float* out = (float*)d_out;

    cudaFuncSetAttribute(k_gemm<0>, cudaFuncAttributeMaxDynamicSharedMemorySize, SMEM_3T);
    cudaFuncSetAttribute(k_gemm<1>, cudaFuncAttributeMaxDynamicSharedMemorySize, SMEM_3T);
    cudaFuncSetAttribute(k_gemm<2>, cudaFuncAttributeMaxDynamicSharedMemorySize, SMEM_2T);
    cudaFuncSetAttribute(k_gemm<3>, cudaFuncAttributeMaxDynamicSharedMemorySize, SMEM_2T);

    __half *hh, *hl, *wh, *wl;
    cudaGetSymbolAddress((void**)&hh, g_hh);
    cudaGetSymbolAddress((void**)&hl, g_hl);
    cudaGetSymbolAddress((void**)&wh, g_Wh);
    cudaGetSymbolAddress((void**)&wl, g_Wl);

    // 0) pre-split inputs
    k_split<<<(MROWS * Cc / 4) / 256, 256>>>(h,   hh, hl, MROWS * Cc / 4);
    k_split<<<(Cc * Cc / 4) / 256,    256>>>(W_w, wh, wl, Cc * Cc / 4);
    k_splitMt<<<1, 256>>>(Mmat);

    // 1) X = h @ W^T + b          -> X_hi/X_lo          (3-term f16)
    k_gemm<0><<<dim3(Hh, MROWS / 128), 128, SMEM_3T>>>(W_b);
    // 2) X^T                      -> VT_hi/VT_lo
    k_transpose<<<dim3(Nn / 32, Dd / 32, BHn), dim3(32, 8)>>>();
    // 3) XM = X @ M               -> XM_hi               (3-term f16)
    k_gemm<1><<<dim3((BHn * Nn) / 128), 128, SMEM_3T>>>(nullptr);
    // 4) P = exp(S - 12), lpart   -> g_Ph (fp16), g_L    (2-term f16)
    k_gemm<2><<<dim3(Nn / 128, Nn / 128, BHn), 128, SMEM_2T>>>(nullptr);
    // 5) O = (P @ V) / l          -> g_O                 (2-term f16)
    k_gemm<3><<<dim3(Nn / 128, BHn), 128, SMEM_2T>>>(nullptr);
    // 6) LayerNorm + GELU         -> out
    k_ln_gelu<<<MROWS, 256>>>(gamma, beta, out);
}

// round 13
// speedup vs baseline: 1.2570x; 1.2129x over previous
#include <cuda_runtime.h>
#include <cuda_fp16.h>
#include <stdint.h>
#include <math.h>

// Fixed shapes for GraphAttentionLayer_18021682774974
#define Bb  32
#define Nn  1024
#define Cc  1024
#define Hh  8
#define Dd  128
#define BHn 256
#define MROWS (Bb * Nn)              // 32768
#define XW  (BHn * Nn * Dd)          // 33.5M

// log-domain shift so P = exp(S - PSHIFT) fits fp16 (S_max ~ 16 << 23.1).
#define PSHIFT 12.0f

// Pre-split half operands + scratch (device globals; no cudaMalloc allowed)
__device__ __half g_hh [MROWS * Cc], g_hl [MROWS * Cc];   // h split
__device__ __half g_Wh [Cc * Cc],    g_Wl [Cc * Cc];      // W split
__device__ __half g_Mth[Dd * Dd],    g_Mtl[Dd * Dd];      // M^T split
__device__ __half g_Xh [XW], g_Xl [XW];                   // X  [z][n][d]
__device__ __half g_XMh[XW];                              // XM hi only
__device__ __half g_VTh[XW];                              // X^T hi [z][d][n]
__device__ __half g_Ph [(size_t)BHn * Nn * Nn];           // P fp16 (512MB)
__device__ float  g_L  [BHn * Nn * 8];                    // row-sum partials
__device__ float  g_O  [XW];                              // attention out

// ---------------------------------------------------------------------------
__device__ __forceinline__ uint32_t smem_u32(const void* p) {
    uint32_t a;
    asm("{ .reg .u64 t; cvta.to.shared.u64 t, %1; cvt.u32.u64 %0, t; }"
        : "=r"(a) : "l"(p));
    return a;
}
__device__ __forceinline__ void cp16(uint32_t sa, const void* gp) {
    asm volatile("cp.async.cg.shared.global [%0], [%1], 16;" :: "r"(sa), "l"(gp));
}
#define CP_COMMIT() asm volatile("cp.async.commit_group;" ::: "memory")
#define CP_WAIT1()  asm volatile("cp.async.wait_group 1;" ::: "memory")

#define MMA_F16(d, a, b)                                                      \
    asm volatile("mma.sync.aligned.m16n8k16.row.col.f32.f16.f16.f32 "         \
                 "{%0,%1,%2,%3}, {%4,%5,%6,%7}, {%8,%9}, {%0,%1,%2,%3};"      \
                 : "+f"((d)[0]), "+f"((d)[1]), "+f"((d)[2]), "+f"((d)[3])     \
                 : "r"((a)[0]), "r"((a)[1]), "r"((a)[2]), "r"((a)[3]),        \
                   "r"((b)[0]), "r"((b)[1]))

// ---------------------------------------------------------------------------
// Elementwise fp32 -> fp16 hi/lo split (vectorized float4)
// ---------------------------------------------------------------------------
__global__ void __launch_bounds__(256) k_split(const float* __restrict__ src,
                                               __half* __restrict__ hi,
                                               __half* __restrict__ lo, int n4)
{
    int i = blockIdx.x * 256 + threadIdx.x;
    if (i >= n4) return;
    float4 v = ((const float4*)src)[i];
    __half h0 = __float2half_rn(v.x), h1 = __float2half_rn(v.y);
    __half h2 = __float2half_rn(v.z), h3 = __float2half_rn(v.w);
    ((__half2*)hi)[2*i]   = __halves2half2(h0, h1);
    ((__half2*)hi)[2*i+1] = __halves2half2(h2, h3);
    ((__half2*)lo)[2*i]   = __floats2half2_rn(v.x - __half2float(h0),
                                              v.y - __half2float(h1));
    ((__half2*)lo)[2*i+1] = __floats2half2_rn(v.z - __half2float(h2),
                                              v.w - __half2float(h3));
}

// M^T split (tiny, one block)
__global__ void __launch_bounds__(256) k_splitMt(const float* __restrict__ M)
{
    for (int i = threadIdx.x; i < Dd * Dd; i += 256) {
        int e = i >> 7, k = i & 127;
        float v = M[k * Dd + e];
        __half h = __float2half_rn(v);
        g_Mth[i] = h;
        g_Mtl[i] = __float2half_rn(v - __half2float(h));
    }
}

// ===========================================================================
// Unified f16 GEMM, cp.async 3-stage pipeline (round-10 proven body).
// D[128x128] = A @ B^T. CTA = 128 threads (4 warps, 2x2 of 64x64 warp tiles),
// 2 CTAs/SM. K-chunk = 32 halfs. 16B chunk (row r, ch) at (ch ^ ((r>>1)&3)).
// Stage words: m0/1: AH[2048] AL[2048] BH[2048] BL[2048] = 8192
//              m2:   AH[2048]          BH[2048] BL[2048] = 6144
//              m3:   AH[2048]          BH[2048]          = 4096
// MODE 0: X  = h @ W^T + bias   3-term  K=1024
// MODE 1: XM = X @ M            3-term  K=128
// MODE 2: P  = exp(XMh@X^T-12)  2-term  K=128
// MODE 3: O  = (P @ Vhi) / l    1-term  K=1024
// ===========================================================================
template<int MODE>
__global__ void __launch_bounds__(128, 2) k_gemm(const float* __restrict__ bias)
{
    extern __shared__ uint32_t smw[];
    constexpr bool ALO = (MODE <= 1);               // A has a lo plane
    constexpr bool BLO = (MODE != 3);               // B has a lo plane
    constexpr int  STG = ALO ? 8192 : (BLO ? 6144 : 4096);
    constexpr int  NC  = (MODE == 0 || MODE == 3) ? 32 : 4;
    constexpr int  BOFF = ALO ? 4096 : 2048;        // B offset in words

    const int tid = threadIdx.x;
    const int wid = tid >> 5, lane = tid & 31;
    const int wm  = wid >> 1, wn = wid & 1;
    const int g   = lane >> 2, t = lane & 3;
    const uint32_t xr = (uint32_t)((g & 6) << 1);

    int m0 = 0, n0 = 0; size_t z = 0;
    const __half *Ah = nullptr, *Al = nullptr, *Bh = nullptr, *Bl = nullptr;
    int Ast = 0, Bst = 0;
    if (MODE == 0) {
        m0 = blockIdx.y * 128; n0 = blockIdx.x * 128;
        Ah = g_hh + (size_t)m0 * Cc;  Al = g_hl + (size_t)m0 * Cc;  Ast = Cc;
        Bh = g_Wh + (size_t)n0 * Cc;  Bl = g_Wl + (size_t)n0 * Cc;  Bst = Cc;
    } else if (MODE == 1) {
        m0 = blockIdx.x * 128;
        Ah = g_Xh + (size_t)m0 * Dd;  Al = g_Xl + (size_t)m0 * Dd;  Ast = Dd;
        Bh = g_Mth;                   Bl = g_Mtl;                   Bst = Dd;
    } else if (MODE == 2) {
        z = blockIdx.z; m0 = blockIdx.y * 128; n0 = blockIdx.x * 128;
        Ah = g_XMh + (z * Nn + m0) * (size_t)Dd;  Ast = Dd;
        Bh = g_Xh  + (z * Nn + n0) * (size_t)Dd;
        Bl = g_Xl  + (z * Nn + n0) * (size_t)Dd;  Bst = Dd;
    } else {
        z = blockIdx.y; m0 = blockIdx.x * 128;
        Ah = g_Ph  + (z * Nn + m0) * (size_t)Nn;  Ast = Nn;
        Bh = g_VTh + z * (size_t)(Dd * Nn);       Bst = Nn;
    }

    float acc[4][8][4];
    #pragma unroll
    for (int a = 0; a < 4; ++a)
        #pragma unroll
        for (int b = 0; b < 8; ++b)
            #pragma unroll
            for (int c = 0; c < 4; ++c) acc[a][b][c] = 0.f;

    const uint32_t sbase = smem_u32(smw);
    auto load_stage = [&](int st, int k0) {
        const uint32_t sb = sbase + (uint32_t)st * STG * 4;
        #pragma unroll
        for (int i = 0; i < 4; ++i) {                       // A: 128r x 4 chunks
            int idx = tid + (i << 7);
            int r = idx >> 2, ch = idx & 3;
            uint32_t d = sb + (uint32_t)(r * 64 + ((ch ^ ((r >> 1) & 3)) << 4));
            const size_t go = (size_t)r * Ast + k0 + ch * 8;
            cp16(d, Ah + go);
            if (ALO) cp16(d + 2048 * 4, Al + go);
        }
        #pragma unroll
        for (int i = 0; i < 4; ++i) {                       // B: 128r x 4 chunks
            int idx = tid + (i << 7);
            int r = idx >> 2, ch = idx & 3;
            uint32_t d = sb + (uint32_t)(BOFF * 4)
                       + (uint32_t)(r * 64 + ((ch ^ ((r >> 1) & 3)) << 4));
            const size_t go = (size_t)r * Bst + k0 + ch * 8;
            cp16(d, Bh + go);
            if (BLO) cp16(d + 2048 * 4, Bl + go);
        }
    };

    // prologue
    load_stage(0, 0);  CP_COMMIT();
    load_stage(1, 32); CP_COMMIT();

    for (int c = 0; c < NC; ++c) {
        CP_WAIT1();
        __syncthreads();
        if (c + 2 < NC) load_stage((c + 2) % 3, (c + 2) * 32);
        CP_COMMIT();

        const int st = c % 3;
        const uint32_t* AH = smw + st * STG;
        const uint32_t* AL = AH + 2048;
        const uint32_t* BH = smw + st * STG + BOFF;
        const uint32_t* BL = BH + 2048;

        #pragma unroll
        for (int ks = 0; ks < 2; ++ks) {
            const uint32_t w0 = (uint32_t)(ks * 8 + t) ^ xr;
            const uint32_t w1 = (uint32_t)(ks * 8 + t + 4) ^ xr;
            uint32_t ah[4][4], bb[8][2];
            #pragma unroll
            for (int mf = 0; mf < 4; ++mf) {
                int R0 = (wm * 64 + mf * 16 + g) * 16, R1 = R0 + 128;
                ah[mf][0] = AH[R0 + w0];
                ah[mf][1] = AH[R1 + w0];
                ah[mf][2] = AH[R0 + w1];
                ah[mf][3] = AH[R1 + w1];
            }
            #pragma unroll
            for (int nf = 0; nf < 8; ++nf) {
                int Rn = (wn * 64 + nf * 8 + g) * 16;
                bb[nf][0] = BH[Rn + w0];
                bb[nf][1] = BH[Rn + w1];
            }
            // term 1: A_hi x B_hi
            #pragma unroll
            for (int mf = 0; mf < 4; ++mf)
                #pragma unroll
                for (int nf = 0; nf < 8; ++nf)
                    MMA_F16(acc[mf][nf], ah[mf], bb[nf]);
            // term 3 (3-term modes): A_lo x B_hi   (B_hi still live)
            if (ALO) {
                uint32_t al[4][4];
                #pragma unroll
                for (int mf = 0; mf < 4; ++mf) {
                    int R0 = (wm * 64 + mf * 16 + g) * 16, R1 = R0 + 128;
                    al[mf][0] = AL[R0 + w0];
                    al[mf][1] = AL[R1 + w0];
                    al[mf][2] = AL[R0 + w1];
                    al[mf][3] = AL[R1 + w1];
                }
                #pragma unroll
                for (int mf = 0; mf < 4; ++mf)
                    #pragma unroll
                    for (int nf = 0; nf < 8; ++nf)
                        MMA_F16(acc[mf][nf], al[mf], bb[nf]);
            }
            // term 2: A_hi x B_lo
            if (BLO) {
                #pragma unroll
                for (int nf = 0; nf < 8; ++nf) {
                    int Rn = (wn * 64 + nf * 8 + g) * 16;
                    bb[nf][0] = BL[Rn + w0];
                    bb[nf][1] = BL[Rn + w1];
                }
                #pragma unroll
                for (int mf = 0; mf < 4; ++mf)
                    #pragma unroll
                    for (int nf = 0; nf < 8; ++nf)
                        MMA_F16(acc[mf][nf], ah[mf], bb[nf]);
            }
        }
    }
    __syncthreads();

    // ---- epilogue ----
    if (MODE == 0) {
        const int head = blockIdx.x;
        #pragma unroll
        for (int mf = 0; mf < 4; ++mf)
            #pragma unroll
            for (int hh = 0; hh < 2; ++hh) {
                int m = m0 + wm * 64 + mf * 16 + g + 8 * hh;
                int bidx = m >> 10, tok = m & 1023;
                size_t ro = (((size_t)bidx * Hh + head) * Nn + tok) * Dd;
                #pragma unroll
                for (int nf = 0; nf < 8; ++nf) {
                    int col = wn * 64 + nf * 8 + 2 * t;
                    float v0 = acc[mf][nf][2*hh+0] + bias[n0 + col];
                    float v1 = acc[mf][nf][2*hh+1] + bias[n0 + col + 1];
                    __half h0 = __float2half_rn(v0), h1 = __float2half_rn(v1);
                    *(__half2*)(g_Xh + ro + col) = __halves2half2(h0, h1);
                    *(__half2*)(g_Xl + ro + col) =
                        __floats2half2_rn(v0 - __half2float(h0),
                                          v1 - __half2float(h1));
                }
            }
    } else if (MODE == 1) {
        #pragma unroll
        for (int mf = 0; mf < 4; ++mf)
            #pragma unroll
            for (int hh = 0; hh < 2; ++hh) {
                size_t ro = (size_t)(m0 + wm * 64 + mf * 16 + g + 8 * hh) * Dd;
                #pragma unroll
                for (int nf = 0; nf < 8; ++nf) {
                    int col = wn * 64 + nf * 8 + 2 * t;
                    __half h0 = __float2half_rn(acc[mf][nf][2*hh+0]);
                    __half h1 = __float2half_rn(acc[mf][nf][2*hh+1]);
                    *(__half2*)(g_XMh + ro + col) = __halves2half2(h0, h1);
                }
            }
    } else if (MODE == 2) {
        float rsum[4][2];
        #pragma unroll
        for (int mf = 0; mf < 4; ++mf) { rsum[mf][0] = 0.f; rsum[mf][1] = 0.f; }
        #pragma unroll
        for (int mf = 0; mf < 4; ++mf)
            #pragma unroll
            for (int hh = 0; hh < 2; ++hh) {
                int rm = wm * 64 + mf * 16 + g + 8 * hh;
                __half* dst = g_Ph + (z * Nn + m0 + rm) * (size_t)Nn + n0;
                #pragma unroll
                for (int nf = 0; nf < 8; ++nf) {
                    int col = wn * 64 + nf * 8 + 2 * t;
                    __half p0 = __float2half_rn(__expf(acc[mf][nf][2*hh+0] - PSHIFT));
                    __half p1 = __float2half_rn(__expf(acc[mf][nf][2*hh+1] - PSHIFT));
                    rsum[mf][hh] += __half2float(p0) + __half2float(p1);
                    *(__half2*)(dst + col) = __halves2half2(p0, p1);
                }
            }
        float* ssum = (float*)smw;   // alias stage smem (compute done)
        #pragma unroll
        for (int mf = 0; mf < 4; ++mf)
            #pragma unroll
            for (int hh = 0; hh < 2; ++hh) {
                float s = rsum[mf][hh];
                s += __shfl_xor_sync(0xffffffffu, s, 1);
                s += __shfl_xor_sync(0xffffffffu, s, 2);
                if (t == 0)
                    ssum[(wm * 64 + mf * 16 + g + 8 * hh) * 2 + wn] = s;
            }
        __syncthreads();
        {
            float l = ssum[tid * 2] + ssum[tid * 2 + 1];
            g_L[(z * Nn + m0 + tid) * 8 + blockIdx.x] = l;
        }
    } else {  // MODE 3 (PV)
        #pragma unroll
        for (int mf = 0; mf < 4; ++mf)
            #pragma unroll
            for (int hh = 0; hh < 2; ++hh) {
                size_t row = z * Nn + m0 + wm * 64 + mf * 16 + g + 8 * hh;
                const float* lp = g_L + row * 8;
                float l = ((lp[0] + lp[1]) + (lp[2] + lp[3]))
                        + ((lp[4] + lp[5]) + (lp[6] + lp[7]));
                float inv = 1.f / l;
                float* dst = g_O + row * (size_t)Dd;
                #pragma unroll
                for (int nf = 0; nf < 8; ++nf) {
                    int col = wn * 64 + nf * 8 + 2 * t;
                    *(float2*)(dst + col) =
                        make_float2(acc[mf][nf][2*hh+0] * inv,
                                    acc[mf][nf][2*hh+1] * inv);
                }
            }
    }
}

// ---------------------------------------------------------------------------
// Transpose X_hi -> VT_hi  ([z][n][d] -> [z][d][n])
// ---------------------------------------------------------------------------
__global__ void __launch_bounds__(256) k_transpose()
{
    __shared__ __half th[32][33];
    const int z  = blockIdx.z;
    const int d0 = blockIdx.y << 5;
    const int nb = blockIdx.x << 5;
    const int lx = threadIdx.x, ly = threadIdx.y;
    const __half* sh = g_Xh + (size_t)z * Nn * Dd;
    #pragma unroll
    for (int i = 0; i < 32; i += 8)
        th[ly + i][lx] = sh[(size_t)(nb + ly + i) * Dd + d0 + lx];
    __syncthreads();
    __half* dh = g_VTh + (size_t)z * Dd * Nn;
    #pragma unroll
    for (int i = 0; i < 32; i += 8)
        dh[(size_t)(d0 + ly + i) * Nn + nb + lx] = th[lx][ly + i];
}

// ---------------------------------------------------------------------------
// LayerNorm + exact GELU over c (gather heads)
// ---------------------------------------------------------------------------
__global__ void __launch_bounds__(256) k_ln_gelu(const float* __restrict__ gamma,
                                                 const float* __restrict__ beta,
                                                 float* __restrict__ out)
{
    const int row = blockIdx.x;
    const int bbi = row >> 10, nn = row & 1023;
    const int tid = threadIdx.x;
    const int c0 = tid * 4, head = c0 >> 7, dd = c0 & 127;

    const float* src = g_O + (((size_t)bbi * Hh + head) * Nn + nn) * Dd + dd;
    float4 v = *(const float4*)src;

    float s = v.x + v.y + v.z + v.w;
    float q = v.x*v.x + v.y*v.y + v.z*v.z + v.w*v.w;
    #pragma unroll
    for (int off = 16; off >= 1; off >>= 1) {
        s += __shfl_xor_sync(0xffffffffu, s, off);
        q += __shfl_xor_sync(0xffffffffu, q, off);
    }
    __shared__ float ss[8], sq[8];
    if ((tid & 31) == 0) { ss[tid >> 5] = s; sq[tid >> 5] = q; }
    __syncthreads();
    float st = 0.f, qt = 0.f;
    #pragma unroll
    for (int k = 0; k < 8; ++k) { st += ss[k]; qt += sq[k]; }

    const float mean = st * (1.f / (float)Cc);
    const float var  = qt * (1.f / (float)Cc) - mean * mean;
    const float rstd = rsqrtf(var + 1e-5f);

    float4 gm = *(const float4*)(gamma + c0);
    float4 be = *(const float4*)(beta + c0);
    float y0 = (v.x - mean) * rstd * gm.x + be.x;
    float y1 = (v.y - mean) * rstd * gm.y + be.y;
    float y2 = (v.z - mean) * rstd * gm.z + be.z;
    float y3 = (v.w - mean) * rstd * gm.w + be.w;

    const float k2 = 0.70710678118654752440f;
    float4 rr;
    rr.x = 0.5f * y0 * (1.f + erff(y0 * k2));
    rr.y = 0.5f * y1 * (1.f + erff(y1 * k2));
    rr.z = 0.5f * y2 * (1.f + erff(y2 * k2));
    rr.w = 0.5f * y3 * (1.f + erff(y3 * k2));
    *(float4*)(out + (size_t)row * Cc + c0) = rr;
}

// ---------------------------------------------------------------------------
#define SMEM_3T (3 * 8192 * 4)    // 98304 B  (modes 0,1)
#define SMEM_M2 (3 * 6144 * 4)    // 73728 B  (mode 2)
#define SMEM_M3 (3 * 4096 * 4)    // 49152 B  (mode 3)

extern "C" void kernel_launch(void* const* d_in, const int* in_sizes, int n_in,
                              void* d_out, int out_size)
{
    const float* h     = (const float*)d_in[0];
    const float* W_w   = (const float*)d_in[1];
    const float* W_b   = (const float*)d_in[2];
    const float* Mmat  = (const float*)d_in[3];
    const float* gamma = (const float*)d_in[4];
    const float* beta  = (const float*)d_in[5];
    float* out = (float*)d_out;

    cudaFuncSetAttribute(k_gemm<0>, cudaFuncAttributeMaxDynamicSharedMemorySize, SMEM_3T);
    cudaFuncSetAttribute(k_gemm<1>, cudaFuncAttributeMaxDynamicSharedMemorySize, SMEM_3T);
    cudaFuncSetAttribute(k_gemm<2>, cudaFuncAttributeMaxDynamicSharedMemorySize, SMEM_M2);
    cudaFuncSetAttribute(k_gemm<3>, cudaFuncAttributeMaxDynamicSharedMemorySize, SMEM_M3);

    __half *hh, *hl, *wh, *wl;
    cudaGetSymbolAddress((void**)&hh, g_hh);
    cudaGetSymbolAddress((void**)&hl, g_hl);
    cudaGetSymbolAddress((void**)&wh, g_Wh);
    cudaGetSymbolAddress((void**)&wl, g_Wl);

    // 0) pre-split inputs
    k_split<<<(MROWS * Cc / 4) / 256, 256>>>(h,   hh, hl, MROWS * Cc / 4);
    k_split<<<(Cc * Cc / 4) / 256,    256>>>(W_w, wh, wl, Cc * Cc / 4);
    k_splitMt<<<1, 256>>>(Mmat);

    // 1) X = h @ W^T + b          -> X_hi/X_lo          (3-term f16)
    k_gemm<0><<<dim3(Hh, MROWS / 128), 128, SMEM_3T>>>(W_b);
    // 2) X^T (hi only)            -> VT_hi
    k_transpose<<<dim3(Nn / 32, Dd / 32, BHn), dim3(32, 8)>>>();
    // 3) XM = X @ M               -> XM_hi               (3-term f16)
    k_gemm<1><<<dim3((BHn * Nn) / 128), 128, SMEM_3T>>>(nullptr);
    // 4) P = exp(S - 12), lpart   -> g_Ph (fp16), g_L    (2-term f16)
    k_gemm<2><<<dim3(Nn / 128, Nn / 128, BHn), 128, SMEM_M2>>>(nullptr);
    // 5) O = (P @ Vhi) / l        -> g_O                 (1-term f16)
    k_gemm<3><<<dim3(Nn / 128, BHn), 128, SMEM_M3>>>(nullptr);
    // 6) LayerNorm + GELU         -> out
    k_ln_gelu<<<MROWS, 256>>>(gamma, beta, out);
}

// round 14
// speedup vs baseline: 1.3096x; 1.0418x over previous
#include <cuda_runtime.h>
#include <cuda_fp16.h>
#include <stdint.h>
#include <math.h>

// Fixed shapes for GraphAttentionLayer_18021682774974
#define Bb  32
#define Nn  1024
#define Cc  1024
#define Hh  8
#define Dd  128
#define BHn 256
#define MROWS (Bb * Nn)              // 32768
#define XW  (BHn * Nn * Dd)          // 33.5M

// log-domain shift so P = exp(S - PSHIFT) fits fp16 (S_max ~ 16 << 23.1).
// Cancels exactly in O = (P@V) / rowsum(P).
#define PSHIFT 12.0f

// Pre-split half operands + scratch (device globals; no cudaMalloc allowed)
__device__ __half g_hh [MROWS * Cc], g_hl [MROWS * Cc];   // h split
__device__ __half g_Wh [Cc * Cc],    g_Wl [Cc * Cc];      // W split
__device__ __half g_Mth[Dd * Dd],    g_Mtl[Dd * Dd];      // M^T split
__device__ __half g_Xh [XW], g_Xl [XW];                   // X  [z][n][d]
__device__ __half g_XMh[XW];                              // XM hi only
__device__ __half g_VTh[XW];                              // X^T hi [z][d][n]
__device__ float  g_O  [XW];                              // attention out

// ---------------------------------------------------------------------------
__device__ __forceinline__ uint32_t smem_u32(const void* p) {
    uint32_t a;
    asm("{ .reg .u64 t; cvta.to.shared.u64 t, %1; cvt.u32.u64 %0, t; }"
        : "=r"(a) : "l"(p));
    return a;
}
__device__ __forceinline__ void cp16(uint32_t sa, const void* gp) {
    asm volatile("cp.async.cg.shared.global [%0], [%1], 16;" :: "r"(sa), "l"(gp));
}
#define CP_COMMIT() asm volatile("cp.async.commit_group;" ::: "memory")
#define CP_WAIT1()  asm volatile("cp.async.wait_group 1;" ::: "memory")
#define CP_WAIT0()  asm volatile("cp.async.wait_group 0;" ::: "memory")

#define MMA_F16(d, a, b)                                                      \
    asm volatile("mma.sync.aligned.m16n8k16.row.col.f32.f16.f16.f32 "         \
                 "{%0,%1,%2,%3}, {%4,%5,%6,%7}, {%8,%9}, {%0,%1,%2,%3};"      \
                 : "+f"((d)[0]), "+f"((d)[1]), "+f"((d)[2]), "+f"((d)[3])     \
                 : "r"((a)[0]), "r"((a)[1]), "r"((a)[2]), "r"((a)[3]),        \
                   "r"((b)[0]), "r"((b)[1]))

// ---------------------------------------------------------------------------
// Elementwise fp32 -> fp16 hi/lo split (vectorized float4)
// ---------------------------------------------------------------------------
__global__ void __launch_bounds__(256) k_split(const float* __restrict__ src,
                                               __half* __restrict__ hi,
                                               __half* __restrict__ lo, int n4)
{
    int i = blockIdx.x * 256 + threadIdx.x;
    if (i >= n4) return;
    float4 v = ((const float4*)src)[i];
    __half h0 = __float2half_rn(v.x), h1 = __float2half_rn(v.y);
    __half h2 = __float2half_rn(v.z), h3 = __float2half_rn(v.w);
    ((__half2*)hi)[2*i]   = __halves2half2(h0, h1);
    ((__half2*)hi)[2*i+1] = __halves2half2(h2, h3);
    ((__half2*)lo)[2*i]   = __floats2half2_rn(v.x - __half2float(h0),
                                              v.y - __half2float(h1));
    ((__half2*)lo)[2*i+1] = __floats2half2_rn(v.z - __half2float(h2),
                                              v.w - __half2float(h3));
}

// M^T split (tiny, one block)
__global__ void __launch_bounds__(256) k_splitMt(const float* __restrict__ M)
{
    for (int i = threadIdx.x; i < Dd * Dd; i += 256) {
        int e = i >> 7, k = i & 127;
        float v = M[k * Dd + e];
        __half h = __float2half_rn(v);
        g_Mth[i] = h;
        g_Mtl[i] = __float2half_rn(v - __half2float(h));
    }
}

// ===========================================================================
// f16 GEMM (proven round-10 body), modes 0,1 only.
// D[128x128] = A @ B^T. 128 threads (4 warps, 2x2 of 64x64), 2 CTAs/SM.
// Stage = AH[2048] AL[2048] BH[2048] BL[2048] words; 3 stages.
// MODE 0: X  = h @ W^T + bias   3-term  K=1024
// MODE 1: XM = X @ M            3-term  K=128
// ===========================================================================
template<int MODE>
__global__ void __launch_bounds__(128, 2) k_gemm(const float* __restrict__ bias)
{
    extern __shared__ uint32_t smw[];
    constexpr int STG = 8192;
    constexpr int NC  = (MODE == 0) ? 32 : 4;

    const int tid = threadIdx.x;
    const int wid = tid >> 5, lane = tid & 31;
    const int wm  = wid >> 1, wn = wid & 1;
    const int g   = lane >> 2, t = lane & 3;
    const uint32_t xr = (uint32_t)((g & 6) << 1);

    int m0 = 0, n0 = 0;
    const __half *Ah, *Al, *Bh, *Bl;
    int Ast, Bst;
    if (MODE == 0) {
        m0 = blockIdx.y * 128; n0 = blockIdx.x * 128;
        Ah = g_hh + (size_t)m0 * Cc;  Al = g_hl + (size_t)m0 * Cc;  Ast = Cc;
        Bh = g_Wh + (size_t)n0 * Cc;  Bl = g_Wl + (size_t)n0 * Cc;  Bst = Cc;
    } else {
        m0 = blockIdx.x * 128;
        Ah = g_Xh + (size_t)m0 * Dd;  Al = g_Xl + (size_t)m0 * Dd;  Ast = Dd;
        Bh = g_Mth;                   Bl = g_Mtl;                   Bst = Dd;
    }

    float acc[4][8][4];
    #pragma unroll
    for (int a = 0; a < 4; ++a)
        #pragma unroll
        for (int b = 0; b < 8; ++b)
            #pragma unroll
            for (int c = 0; c < 4; ++c) acc[a][b][c] = 0.f;

    const uint32_t sbase = smem_u32(smw);
    auto load_stage = [&](int st, int k0) {
        const uint32_t sb = sbase + (uint32_t)st * STG * 4;
        #pragma unroll
        for (int i = 0; i < 4; ++i) {
            int idx = tid + (i << 7);
            int r = idx >> 2, ch = idx & 3;
            uint32_t d = sb + (uint32_t)(r * 64 + ((ch ^ ((r >> 1) & 3)) << 4));
            const size_t go = (size_t)r * Ast + k0 + ch * 8;
            cp16(d, Ah + go);
            cp16(d + 2048 * 4, Al + go);
        }
        #pragma unroll
        for (int i = 0; i < 4; ++i) {
            int idx = tid + (i << 7);
            int r = idx >> 2, ch = idx & 3;
            uint32_t d = sb + 4096u * 4
                       + (uint32_t)(r * 64 + ((ch ^ ((r >> 1) & 3)) << 4));
            const size_t go = (size_t)r * Bst + k0 + ch * 8;
            cp16(d, Bh + go);
            cp16(d + 2048 * 4, Bl + go);
        }
    };

    load_stage(0, 0);  CP_COMMIT();
    load_stage(1, 32); CP_COMMIT();

    for (int c = 0; c < NC; ++c) {
        CP_WAIT1();
        __syncthreads();
        if (c + 2 < NC) load_stage((c + 2) % 3, (c + 2) * 32);
        CP_COMMIT();

        const int st = c % 3;
        const uint32_t* AH = smw + st * STG;
        const uint32_t* AL = AH + 2048;
        const uint32_t* BH = smw + st * STG + 4096;
        const uint32_t* BL = BH + 2048;

        #pragma unroll
        for (int ks = 0; ks < 2; ++ks) {
            const uint32_t w0 = (uint32_t)(ks * 8 + t) ^ xr;
            const uint32_t w1 = (uint32_t)(ks * 8 + t + 4) ^ xr;
            uint32_t ah[4][4], bb[8][2];
            #pragma unroll
            for (int mf = 0; mf < 4; ++mf) {
                int R0 = (wm * 64 + mf * 16 + g) * 16, R1 = R0 + 128;
                ah[mf][0] = AH[R0 + w0];
                ah[mf][1] = AH[R1 + w0];
                ah[mf][2] = AH[R0 + w1];
                ah[mf][3] = AH[R1 + w1];
            }
            #pragma unroll
            for (int nf = 0; nf < 8; ++nf) {
                int Rn = (wn * 64 + nf * 8 + g) * 16;
                bb[nf][0] = BH[Rn + w0];
                bb[nf][1] = BH[Rn + w1];
            }
            #pragma unroll
            for (int mf = 0; mf < 4; ++mf)
                #pragma unroll
                for (int nf = 0; nf < 8; ++nf)
                    MMA_F16(acc[mf][nf], ah[mf], bb[nf]);
            {
                uint32_t al[4][4];
                #pragma unroll
                for (int mf = 0; mf < 4; ++mf) {
                    int R0 = (wm * 64 + mf * 16 + g) * 16, R1 = R0 + 128;
                    al[mf][0] = AL[R0 + w0];
                    al[mf][1] = AL[R1 + w0];
                    al[mf][2] = AL[R0 + w1];
                    al[mf][3] = AL[R1 + w1];
                }
                #pragma unroll
                for (int mf = 0; mf < 4; ++mf)
                    #pragma unroll
                    for (int nf = 0; nf < 8; ++nf)
                        MMA_F16(acc[mf][nf], al[mf], bb[nf]);
            }
            #pragma unroll
            for (int nf = 0; nf < 8; ++nf) {
                int Rn = (wn * 64 + nf * 8 + g) * 16;
                bb[nf][0] = BL[Rn + w0];
                bb[nf][1] = BL[Rn + w1];
            }
            #pragma unroll
            for (int mf = 0; mf < 4; ++mf)
                #pragma unroll
                for (int nf = 0; nf < 8; ++nf)
                    MMA_F16(acc[mf][nf], ah[mf], bb[nf]);
        }
    }
    __syncthreads();

    if (MODE == 0) {
        const int head = blockIdx.x;
        #pragma unroll
        for (int mf = 0; mf < 4; ++mf)
            #pragma unroll
            for (int hh = 0; hh < 2; ++hh) {
                int m = m0 + wm * 64 + mf * 16 + g + 8 * hh;
                int bidx = m >> 10, tok = m & 1023;
                size_t ro = (((size_t)bidx * Hh + head) * Nn + tok) * Dd;
                #pragma unroll
                for (int nf = 0; nf < 8; ++nf) {
                    int col = wn * 64 + nf * 8 + 2 * t;
                    float v0 = acc[mf][nf][2*hh+0] + bias[n0 + col];
                    float v1 = acc[mf][nf][2*hh+1] + bias[n0 + col + 1];
                    __half h0 = __float2half_rn(v0), h1 = __float2half_rn(v1);
                    *(__half2*)(g_Xh + ro + col) = __halves2half2(h0, h1);
                    *(__half2*)(g_Xl + ro + col) =
                        __floats2half2_rn(v0 - __half2float(h0),
                                          v1 - __half2float(h1));
                }
            }
    } else {
        #pragma unroll
        for (int mf = 0; mf < 4; ++mf)
            #pragma unroll
            for (int hh = 0; hh < 2; ++hh) {
                size_t ro = (size_t)(m0 + wm * 64 + mf * 16 + g + 8 * hh) * Dd;
                #pragma unroll
                for (int nf = 0; nf < 8; ++nf) {
                    int col = wn * 64 + nf * 8 + 2 * t;
                    __half h0 = __float2half_rn(acc[mf][nf][2*hh+0]);
                    __half h1 = __float2half_rn(acc[mf][nf][2*hh+1]);
                    *(__half2*)(g_XMh + ro + col) = __halves2half2(h0, h1);
                }
            }
    }
}

// ===========================================================================
// Fused attention: per (z, q-tile 128): loop 8 k-tiles:
//   S = Qh @ (Kh+Kl)^T (2-term, K=d=128); P = exp(S-12) -> fp16 smem;
//   O += P @ VT (1-term, K=key); l accumulated in regs. Final: O/l -> g_O.
// 256 threads, 8 warps (2 wm x 4 wn), warp tiles 64x32 for S and O.
// smem tiles (128x128 half, 4 sub-chunks of K32, A/B chunk-swizzled layout):
//   Q@0, KH@8192, KL@16384, VT@24576, P@32768 (words) = 160 KB.
// ===========================================================================
#define QOFF  0
#define KHOFF 8192
#define KLOFF 16384
#define VTOFF 24576
#define POFF  32768
#define SMEM_ATT (40960 * 4)

__global__ void __launch_bounds__(256, 1) k_attn()
{
    extern __shared__ uint32_t smw[];
    const int tid = threadIdx.x;
    const int wid = tid >> 5, lane = tid & 31;
    const int wm = wid >> 2, wn = wid & 3;
    const int g = lane >> 2, t = lane & 3;
    const uint32_t xr = (uint32_t)((g & 6) << 1);
    const uint32_t sbase = smem_u32(smw);
    const size_t z = blockIdx.y;
    const int q0 = blockIdx.x * 128;

    const __half* Qg  = g_XMh + (z * Nn + q0) * (size_t)Dd;
    const __half* Khg = g_Xh  + z * (size_t)Nn * Dd;
    const __half* Klg = g_Xl  + z * (size_t)Nn * Dd;
    const __half* VTg = g_VTh + z * (size_t)Dd * Nn;

    // load one 128x128 half tile (row stride st) into word-offset woff
    auto load_tile = [&](uint32_t woff, const __half* src, int st) {
        #pragma unroll
        for (int i = 0; i < 8; ++i) {
            int idx = tid + (i << 8);
            int r = idx >> 4, ch = idx & 15;
            int kc = ch >> 2, c2 = ch & 3;
            uint32_t d = sbase + woff * 4
                       + (uint32_t)(kc * 8192 + r * 64 + ((c2 ^ ((r >> 1) & 3)) << 4));
            cp16(d, src + (size_t)r * st + kc * 32 + c2 * 8);
        }
    };

    float oacc[4][4][4];
    float rsum[4][2];
    #pragma unroll
    for (int a = 0; a < 4; ++a) {
        rsum[a][0] = 0.f; rsum[a][1] = 0.f;
        #pragma unroll
        for (int b = 0; b < 4; ++b)
            #pragma unroll
            for (int c = 0; c < 4; ++c) oacc[a][b][c] = 0.f;
    }

    // prologue: Q, K0(h,l), VT0
    load_tile(QOFF,  Qg,  Dd);
    load_tile(KHOFF, Khg, Dd);
    load_tile(KLOFF, Klg, Dd);
    load_tile(VTOFF, VTg, Nn);
    CP_COMMIT();
    CP_WAIT0();
    __syncthreads();

    for (int kt = 0; kt < 8; ++kt) {
        if (kt > 0) { CP_WAIT1(); __syncthreads(); }   // K(kt) ready

        // ---- S = Q @ K^T (2-term over B) ----
        float sacc[4][4][4];
        #pragma unroll
        for (int a = 0; a < 4; ++a)
            #pragma unroll
            for (int b = 0; b < 4; ++b)
                #pragma unroll
                for (int c = 0; c < 4; ++c) sacc[a][b][c] = 0.f;

        #pragma unroll
        for (int kc = 0; kc < 4; ++kc) {
            const uint32_t* AH = smw + QOFF  + kc * 2048;
            const uint32_t* BH = smw + KHOFF + kc * 2048;
            const uint32_t* BL = smw + KLOFF + kc * 2048;
            #pragma unroll
            for (int ks = 0; ks < 2; ++ks) {
                const uint32_t w0 = (uint32_t)(ks * 8 + t) ^ xr;
                const uint32_t w1 = (uint32_t)(ks * 8 + t + 4) ^ xr;
                uint32_t ah[4][4], bb[4][2];
                #pragma unroll
                for (int mf = 0; mf < 4; ++mf) {
                    int R0 = (wm * 64 + mf * 16 + g) * 16, R1 = R0 + 128;
                    ah[mf][0] = AH[R0 + w0];
                    ah[mf][1] = AH[R1 + w0];
                    ah[mf][2] = AH[R0 + w1];
                    ah[mf][3] = AH[R1 + w1];
                }
                #pragma unroll
                for (int nf = 0; nf < 4; ++nf) {
                    int Rn = (wn * 32 + nf * 8 + g) * 16;
                    bb[nf][0] = BH[Rn + w0];
                    bb[nf][1] = BH[Rn + w1];
                }
                #pragma unroll
                for (int mf = 0; mf < 4; ++mf)
                    #pragma unroll
                    for (int nf = 0; nf < 4; ++nf)
                        MMA_F16(sacc[mf][nf], ah[mf], bb[nf]);
                #pragma unroll
                for (int nf = 0; nf < 4; ++nf) {
                    int Rn = (wn * 32 + nf * 8 + g) * 16;
                    bb[nf][0] = BL[Rn + w0];
                    bb[nf][1] = BL[Rn + w1];
                }
                #pragma unroll
                for (int mf = 0; mf < 4; ++mf)
                    #pragma unroll
                    for (int nf = 0; nf < 4; ++nf)
                        MMA_F16(sacc[mf][nf], ah[mf], bb[nf]);
            }
        }

        // ---- P = exp(S - 12) -> fp16 smem (A-layout), l partials ----
        #pragma unroll
        for (int mf = 0; mf < 4; ++mf)
            #pragma unroll
            for (int hh = 0; hh < 2; ++hh) {
                int r = wm * 64 + mf * 16 + g + 8 * hh;
                #pragma unroll
                for (int nf = 0; nf < 4; ++nf) {
                    float e0 = __expf(sacc[mf][nf][2*hh+0] - PSHIFT);
                    float e1 = __expf(sacc[mf][nf][2*hh+1] - PSHIFT);
                    __half p0 = __float2half_rn(e0), p1 = __float2half_rn(e1);
                    rsum[mf][hh] += __half2float(p0) + __half2float(p1);
                    __half2 pk = __halves2half2(p0, p1);
                    uint32_t w = (uint32_t)(POFF + wn * 2048 + r * 16
                               + ((nf ^ ((r >> 1) & 3)) << 2) + t);
                    smw[w] = *(uint32_t*)&pk;
                }
            }
        __syncthreads();                              // S reads done, P visible
        if (kt < 7) {
            load_tile(KHOFF, Khg + (size_t)(kt + 1) * 128 * Dd, Dd);
            load_tile(KLOFF, Klg + (size_t)(kt + 1) * 128 * Dd, Dd);
            CP_COMMIT();
            CP_WAIT1();                               // VT(kt) ready
        } else {
            CP_WAIT0();
        }
        __syncthreads();

        // ---- O += P @ VT ----
        #pragma unroll
        for (int kc = 0; kc < 4; ++kc) {
            const uint32_t* AH = smw + POFF  + kc * 2048;
            const uint32_t* BH = smw + VTOFF + kc * 2048;
            #pragma unroll
            for (int ks = 0; ks < 2; ++ks) {
                const uint32_t w0 = (uint32_t)(ks * 8 + t) ^ xr;
                const uint32_t w1 = (uint32_t)(ks * 8 + t + 4) ^ xr;
                uint32_t ah[4][4], bb[4][2];
                #pragma unroll
                for (int mf = 0; mf < 4; ++mf) {
                    int R0 = (wm * 64 + mf * 16 + g) * 16, R1 = R0 + 128;
                    ah[mf][0] = AH[R0 + w0];
                    ah[mf][1] = AH[R1 + w0];
                    ah[mf][2] = AH[R0 + w1];
                    ah[mf][3] = AH[R1 + w1];
                }
                #pragma unroll
                for (int nf = 0; nf < 4; ++nf) {
                    int Rn = (wn * 32 + nf * 8 + g) * 16;
                    bb[nf][0] = BH[Rn + w0];
                    bb[nf][1] = BH[Rn + w1];
                }
                #pragma unroll
                for (int mf = 0; mf < 4; ++mf)
                    #pragma unroll
                    for (int nf = 0; nf < 4; ++nf)
                        MMA_F16(oacc[mf][nf], ah[mf], bb[nf]);
            }
        }
        __syncthreads();                              // P / VT free
        if (kt < 7) {
            load_tile(VTOFF, VTg + (kt + 1) * 128, Nn);
            CP_COMMIT();
        }
    }

    // ---- final: reduce l, normalize, store ----
    float* ssum = (float*)(smw + POFF);               // P dead (post-PV sync)
    #pragma unroll
    for (int mf = 0; mf < 4; ++mf)
        #pragma unroll
        for (int hh = 0; hh < 2; ++hh) {
            float s = rsum[mf][hh];
            s += __shfl_xor_sync(0xffffffffu, s, 1);
            s += __shfl_xor_sync(0xffffffffu, s, 2);
            if (t == 0)
                ssum[(wm * 64 + mf * 16 + g + 8 * hh) * 4 + wn] = s;
        }
    __syncthreads();
    #pragma unroll
    for (int mf = 0; mf < 4; ++mf)
        #pragma unroll
        for (int hh = 0; hh < 2; ++hh) {
            int r = wm * 64 + mf * 16 + g + 8 * hh;
            const float* lp = ssum + r * 4;
            float inv = 1.f / ((lp[0] + lp[1]) + (lp[2] + lp[3]));
            float* dst = g_O + (z * Nn + q0 + r) * (size_t)Dd;
            #pragma unroll
            for (int nf = 0; nf < 4; ++nf) {
                int col = wn * 32 + nf * 8 + 2 * t;
                *(float2*)(dst + col) =
                    make_float2(oacc[mf][nf][2*hh+0] * inv,
                                oacc[mf][nf][2*hh+1] * inv);
            }
        }
}

// ---------------------------------------------------------------------------
// Transpose X_hi -> VT_hi  ([z][n][d] -> [z][d][n])
// ---------------------------------------------------------------------------
__global__ void __launch_bounds__(256) k_transpose()
{
    __shared__ __half th[32][33];
    const int z  = blockIdx.z;
    const int d0 = blockIdx.y << 5;
    const int nb = blockIdx.x << 5;
    const int lx = threadIdx.x, ly = threadIdx.y;
    const __half* sh = g_Xh + (size_t)z * Nn * Dd;
    #pragma unroll
    for (int i = 0; i < 32; i += 8)
        th[ly + i][lx] = sh[(size_t)(nb + ly + i) * Dd + d0 + lx];
    __syncthreads();
    __half* dh = g_VTh + (size_t)z * Dd * Nn;
    #pragma unroll
    for (int i = 0; i < 32; i += 8)
        dh[(size_t)(d0 + ly + i) * Nn + nb + lx] = th[lx][ly + i];
}

// ---------------------------------------------------------------------------
// LayerNorm + exact GELU over c (gather heads)
// ---------------------------------------------------------------------------
__global__ void __launch_bounds__(256) k_ln_gelu(const float* __restrict__ gamma,
                                                 const float* __restrict__ beta,
                                                 float* __restrict__ out)
{
    const int row = blockIdx.x;
    const int bbi = row >> 10, nn = row & 1023;
    const int tid = threadIdx.x;
    const int c0 = tid * 4, head = c0 >> 7, dd = c0 & 127;

    const float* src = g_O + (((size_t)bbi * Hh + head) * Nn + nn) * Dd + dd;
    float4 v = *(const float4*)src;

    float s = v.x + v.y + v.z + v.w;
    float q = v.x*v.x + v.y*v.y + v.z*v.z + v.w*v.w;
    #pragma unroll
    for (int off = 16; off >= 1; off >>= 1) {
        s += __shfl_xor_sync(0xffffffffu, s, off);
        q += __shfl_xor_sync(0xffffffffu, q, off);
    }
    __shared__ float ss[8], sq[8];
    if ((tid & 31) == 0) { ss[tid >> 5] = s; sq[tid >> 5] = q; }
    __syncthreads();
    float st = 0.f, qt = 0.f;
    #pragma unroll
    for (int k = 0; k < 8; ++k) { st += ss[k]; qt += sq[k]; }

    const float mean = st * (1.f / (float)Cc);
    const float var  = qt * (1.f / (float)Cc) - mean * mean;
    const float rstd = rsqrtf(var + 1e-5f);

    float4 gm = *(const float4*)(gamma + c0);
    float4 be = *(const float4*)(beta + c0);
    float y0 = (v.x - mean) * rstd * gm.x + be.x;
    float y1 = (v.y - mean) * rstd * gm.y + be.y;
    float y2 = (v.z - mean) * rstd * gm.z + be.z;
    float y3 = (v.w - mean) * rstd * gm.w + be.w;

    const float k2 = 0.70710678118654752440f;
    float4 rr;
    rr.x = 0.5f * y0 * (1.f + erff(y0 * k2));
    rr.y = 0.5f * y1 * (1.f + erff(y1 * k2));
    rr.z = 0.5f * y2 * (1.f + erff(y2 * k2));
    rr.w = 0.5f * y3 * (1.f + erff(y3 * k2));
    *(float4*)(out + (size_t)row * Cc + c0) = rr;
}

// ---------------------------------------------------------------------------
#define SMEM_3T (3 * 8192 * 4)    // 98304 B  (modes 0,1)

extern "C" void kernel_launch(void* const* d_in, const int* in_sizes, int n_in,
                              void* d_out, int out_size)
{
    const float* h     = (const float*)d_in[0];
    const float* W_w   = (const float*)d_in[1];
    const float* W_b   = (const float*)d_in[2];
    const float* Mmat  = (const float*)d_in[3];
    const float* gamma = (const float*)d_in[4];
    const float* beta  = (const float*)d_in[5];
    float* out = (float*)d_out;

    cudaFuncSetAttribute(k_gemm<0>, cudaFuncAttributeMaxDynamicSharedMemorySize, SMEM_3T);
    cudaFuncSetAttribute(k_gemm<1>, cudaFuncAttributeMaxDynamicSharedMemorySize, SMEM_3T);
    cudaFuncSetAttribute(k_attn,    cudaFuncAttributeMaxDynamicSharedMemorySize, SMEM_ATT);

    __half *hh, *hl, *wh, *wl;
    cudaGetSymbolAddress((void**)&hh, g_hh);
    cudaGetSymbolAddress((void**)&hl, g_hl);
    cudaGetSymbolAddress((void**)&wh, g_Wh);
    cudaGetSymbolAddress((void**)&wl, g_Wl);

    // 0) pre-split inputs
    k_split<<<(MROWS * Cc / 4) / 256, 256>>>(h,   hh, hl, MROWS * Cc / 4);
    k_split<<<(Cc * Cc / 4) / 256,    256>>>(W_w, wh, wl, Cc * Cc / 4);
    k_splitMt<<<1, 256>>>(Mmat);

    // 1) X = h @ W^T + b          -> X_hi/X_lo          (3-term f16)
    k_gemm<0><<<dim3(Hh, MROWS / 128), 128, SMEM_3T>>>(W_b);
    // 2) X^T (hi only)            -> VT_hi
    k_transpose<<<dim3(Nn / 32, Dd / 32, BHn), dim3(32, 8)>>>();
    // 3) XM = X @ M               -> XM_hi               (3-term f16)
    k_gemm<1><<<dim3((BHn * Nn) / 128), 128, SMEM_3T>>>(nullptr);
    // 4+5) fused attention        -> g_O
    k_attn<<<dim3(Nn / 128, BHn), 256, SMEM_ATT>>>();
    // 6) LayerNorm + GELU         -> out
    k_ln_gelu<<<MROWS, 256>>>(gamma, beta, out);
}

// round 16
// speedup vs baseline: 1.5045x; 1.1488x over previous
#include <cuda_runtime.h>
#include <cuda_fp16.h>
#include <stdint.h>
#include <math.h>

// Fixed shapes for GraphAttentionLayer_18021682774974
#define Bb  32
#define Nn  1024
#define Cc  1024
#define Hh  8
#define Dd  128
#define BHn 256
#define MROWS (Bb * Nn)              // 32768
#define XW  (BHn * Nn * Dd)          // 33.5M

// log-domain shift so P = exp(S - PSHIFT) fits fp16 (S_max ~ 16 << 23.1).
// Cancels exactly in O = (P@V) / rowsum(P).
#define PSHIFT 12.0f

// Pre-split half operands + scratch (device globals; no cudaMalloc allowed)
__device__ __half g_hh [MROWS * Cc], g_hl [MROWS * Cc];   // h split
__device__ __half g_Wh [Cc * Cc];                         // W hi only
__device__ __half g_Mth[Dd * Dd],    g_Mtl[Dd * Dd];      // M^T split
__device__ __half g_Xh [XW], g_Xl [XW];                   // X  [z][n][d]
__device__ __half g_XMh[XW];                              // XM hi only
__device__ __half g_VTh[XW];                              // X^T hi [z][d][n]
__device__ float  g_O  [XW];                              // attention out

// ---------------------------------------------------------------------------
__device__ __forceinline__ uint32_t smem_u32(const void* p) {
    uint32_t a;
    asm("{ .reg .u64 t; cvta.to.shared.u64 t, %1; cvt.u32.u64 %0, t; }"
        : "=r"(a) : "l"(p));
    return a;
}
__device__ __forceinline__ void cp16(uint32_t sa, const void* gp) {
    asm volatile("cp.async.cg.shared.global [%0], [%1], 16;" :: "r"(sa), "l"(gp));
}
#define CP_COMMIT() asm volatile("cp.async.commit_group;" ::: "memory")
#define CP_WAIT1()  asm volatile("cp.async.wait_group 1;" ::: "memory")
#define CP_WAIT0()  asm volatile("cp.async.wait_group 0;" ::: "memory")

#define MMA_F16(d, a, b)                                                      \
    asm volatile("mma.sync.aligned.m16n8k16.row.col.f32.f16.f16.f32 "         \
                 "{%0,%1,%2,%3}, {%4,%5,%6,%7}, {%8,%9}, {%0,%1,%2,%3};"      \
                 : "+f"((d)[0]), "+f"((d)[1]), "+f"((d)[2]), "+f"((d)[3])     \
                 : "r"((a)[0]), "r"((a)[1]), "r"((a)[2]), "r"((a)[3]),        \
                   "r"((b)[0]), "r"((b)[1]))

// ---------------------------------------------------------------------------
// Elementwise fp32 -> fp16 hi/lo split (vectorized float4)
// ---------------------------------------------------------------------------
__global__ void __launch_bounds__(256) k_split(const float* __restrict__ src,
                                               __half* __restrict__ hi,
                                               __half* __restrict__ lo, int n4)
{
    int i = blockIdx.x * 256 + threadIdx.x;
    if (i >= n4) return;
    float4 v = ((const float4*)src)[i];
    __half h0 = __float2half_rn(v.x), h1 = __float2half_rn(v.y);
    __half h2 = __float2half_rn(v.z), h3 = __float2half_rn(v.w);
    ((__half2*)hi)[2*i]   = __halves2half2(h0, h1);
    ((__half2*)hi)[2*i+1] = __halves2half2(h2, h3);
    if (lo) {
        ((__half2*)lo)[2*i]   = __floats2half2_rn(v.x - __half2float(h0),
                                                  v.y - __half2float(h1));
        ((__half2*)lo)[2*i+1] = __floats2half2_rn(v.z - __half2float(h2),
                                                  v.w - __half2float(h3));
    }
}

// M^T split (tiny, one block)
__global__ void __launch_bounds__(256) k_splitMt(const float* __restrict__ M)
{
    for (int i = threadIdx.x; i < Dd * Dd; i += 256) {
        int e = i >> 7, k = i & 127;
        float v = M[k * Dd + e];
        __half h = __float2half_rn(v);
        g_Mth[i] = h;
        g_Mtl[i] = __float2half_rn(v - __half2float(h));
    }
}

// ===========================================================================
// f16 GEMM (proven body), modes 0,1.
// D[128x128] = A @ B^T. 128 threads (4 warps, 2x2 of 64x64), 2 CTAs/SM.
// MODE 0: X  = h @ W^T + bias   2-term (hh + lo_A*hi_B)  K=1024
// MODE 1: XM = X @ M            3-term                    K=128
// Stage words: m0: AH[2048] AL[2048] BH[2048]          = 6144
//              m1: AH[2048] AL[2048] BH[2048] BL[2048] = 8192
// ===========================================================================
template<int MODE>
__global__ void __launch_bounds__(128, 2) k_gemm(const float* __restrict__ bias)
{
    extern __shared__ uint32_t smw[];
    constexpr bool BLO = (MODE == 1);               // B has a lo plane
    constexpr int  STG = BLO ? 8192 : 6144;
    constexpr int  NC  = (MODE == 0) ? 32 : 4;
    constexpr int  BOFF = 4096;                     // after AH+AL

    const int tid = threadIdx.x;
    const int wid = tid >> 5, lane = tid & 31;
    const int wm  = wid >> 1, wn = wid & 1;
    const int g   = lane >> 2, t = lane & 3;
    const uint32_t xr = (uint32_t)((g & 6) << 1);

    int m0 = 0, n0 = 0;
    const __half *Ah, *Al, *Bh, *Bl = nullptr;
    int Ast, Bst;
    if (MODE == 0) {
        m0 = blockIdx.y * 128; n0 = blockIdx.x * 128;
        Ah = g_hh + (size_t)m0 * Cc;  Al = g_hl + (size_t)m0 * Cc;  Ast = Cc;
        Bh = g_Wh + (size_t)n0 * Cc;                                Bst = Cc;
    } else {
        m0 = blockIdx.x * 128;
        Ah = g_Xh + (size_t)m0 * Dd;  Al = g_Xl + (size_t)m0 * Dd;  Ast = Dd;
        Bh = g_Mth;                   Bl = g_Mtl;                   Bst = Dd;
    }

    float acc[4][8][4];
    #pragma unroll
    for (int a = 0; a < 4; ++a)
        #pragma unroll
        for (int b = 0; b < 8; ++b)
            #pragma unroll
            for (int c = 0; c < 4; ++c) acc[a][b][c] = 0.f;

    const uint32_t sbase = smem_u32(smw);
    auto load_stage = [&](int st, int k0) {
        const uint32_t sb = sbase + (uint32_t)st * STG * 4;
        #pragma unroll
        for (int i = 0; i < 4; ++i) {
            int idx = tid + (i << 7);
            int r = idx >> 2, ch = idx & 3;
            uint32_t d = sb + (uint32_t)(r * 64 + ((ch ^ ((r >> 1) & 3)) << 4));
            const size_t go = (size_t)r * Ast + k0 + ch * 8;
            cp16(d, Ah + go);
            cp16(d + 2048 * 4, Al + go);
        }
        #pragma unroll
        for (int i = 0; i < 4; ++i) {
            int idx = tid + (i << 7);
            int r = idx >> 2, ch = idx & 3;
            uint32_t d = sb + (uint32_t)(BOFF * 4)
                       + (uint32_t)(r * 64 + ((ch ^ ((r >> 1) & 3)) << 4));
            const size_t go = (size_t)r * Bst + k0 + ch * 8;
            cp16(d, Bh + go);
            if (BLO) cp16(d + 2048 * 4, Bl + go);
        }
    };

    load_stage(0, 0);  CP_COMMIT();
    load_stage(1, 32); CP_COMMIT();

    for (int c = 0; c < NC; ++c) {
        CP_WAIT1();
        __syncthreads();
        if (c + 2 < NC) load_stage((c + 2) % 3, (c + 2) * 32);
        CP_COMMIT();

        const int st = c % 3;
        const uint32_t* AH = smw + st * STG;
        const uint32_t* AL = AH + 2048;
        const uint32_t* BH = smw + st * STG + BOFF;
        const uint32_t* BL = BH + 2048;

        #pragma unroll
        for (int ks = 0; ks < 2; ++ks) {
            const uint32_t w0 = (uint32_t)(ks * 8 + t) ^ xr;
            const uint32_t w1 = (uint32_t)(ks * 8 + t + 4) ^ xr;
            uint32_t ah[4][4], bb[8][2];
            #pragma unroll
            for (int mf = 0; mf < 4; ++mf) {
                int R0 = (wm * 64 + mf * 16 + g) * 16, R1 = R0 + 128;
                ah[mf][0] = AH[R0 + w0];
                ah[mf][1] = AH[R1 + w0];
                ah[mf][2] = AH[R0 + w1];
                ah[mf][3] = AH[R1 + w1];
            }
            #pragma unroll
            for (int nf = 0; nf < 8; ++nf) {
                int Rn = (wn * 64 + nf * 8 + g) * 16;
                bb[nf][0] = BH[Rn + w0];
                bb[nf][1] = BH[Rn + w1];
            }
            // term 1: A_hi x B_hi
            #pragma unroll
            for (int mf = 0; mf < 4; ++mf)
                #pragma unroll
                for (int nf = 0; nf < 8; ++nf)
                    MMA_F16(acc[mf][nf], ah[mf], bb[nf]);
            // term 2: A_lo x B_hi   (B_hi still live)
            {
                uint32_t al[4][4];
                #pragma unroll
                for (int mf = 0; mf < 4; ++mf) {
                    int R0 = (wm * 64 + mf * 16 + g) * 16, R1 = R0 + 128;
                    al[mf][0] = AL[R0 + w0];
                    al[mf][1] = AL[R1 + w0];
                    al[mf][2] = AL[R0 + w1];
                    al[mf][3] = AL[R1 + w1];
                }
                #pragma unroll
                for (int mf = 0; mf < 4; ++mf)
                    #pragma unroll
                    for (int nf = 0; nf < 8; ++nf)
                        MMA_F16(acc[mf][nf], al[mf], bb[nf]);
            }
            // term 3 (mode 1 only): A_hi x B_lo
            if (BLO) {
                #pragma unroll
                for (int nf = 0; nf < 8; ++nf) {
                    int Rn = (wn * 64 + nf * 8 + g) * 16;
                    bb[nf][0] = BL[Rn + w0];
                    bb[nf][1] = BL[Rn + w1];
                }
                #pragma unroll
                for (int mf = 0; mf < 4; ++mf)
                    #pragma unroll
                    for (int nf = 0; nf < 8; ++nf)
                        MMA_F16(acc[mf][nf], ah[mf], bb[nf]);
            }
        }
    }
    __syncthreads();

    if (MODE == 0) {
        const int head = blockIdx.x;
        #pragma unroll
        for (int mf = 0; mf < 4; ++mf)
            #pragma unroll
            for (int hh = 0; hh < 2; ++hh) {
                int m = m0 + wm * 64 + mf * 16 + g + 8 * hh;
                int bidx = m >> 10, tok = m & 1023;
                size_t ro = (((size_t)bidx * Hh + head) * Nn + tok) * Dd;
                #pragma unroll
                for (int nf = 0; nf < 8; ++nf) {
                    int col = wn * 64 + nf * 8 + 2 * t;
                    float v0 = acc[mf][nf][2*hh+0] + bias[n0 + col];
                    float v1 = acc[mf][nf][2*hh+1] + bias[n0 + col + 1];
                    __half h0 = __float2half_rn(v0), h1 = __float2half_rn(v1);
                    *(__half2*)(g_Xh + ro + col) = __halves2half2(h0, h1);
                    *(__half2*)(g_Xl + ro + col) =
                        __floats2half2_rn(v0 - __half2float(h0),
                                          v1 - __half2float(h1));
                }
            }
    } else {
        #pragma unroll
        for (int mf = 0; mf < 4; ++mf)
            #pragma unroll
            for (int hh = 0; hh < 2; ++hh) {
                size_t ro = (size_t)(m0 + wm * 64 + mf * 16 + g + 8 * hh) * Dd;
                #pragma unroll
                for (int nf = 0; nf < 8; ++nf) {
                    int col = wn * 64 + nf * 8 + 2 * t;
                    __half h0 = __float2half_rn(acc[mf][nf][2*hh+0]);
                    __half h1 = __float2half_rn(acc[mf][nf][2*hh+1]);
                    *(__half2*)(g_XMh + ro + col) = __halves2half2(h0, h1);
                }
            }
    }
}

// ===========================================================================
// Fused attention (round-14 proven): per (z, q-tile 128): loop 8 k-tiles:
//   S = Qh @ (Kh+Kl)^T (2-term); P = exp(S-12) -> fp16 smem;
//   O += P @ VT (1-term); l in regs. Final: O/l -> g_O.
// 256 threads, 8 warps (2 wm x 4 wn), warp tiles 64x32.
// smem: Q@0, KH@8192, KL@16384, VT@24576, P@32768 (words) = 160 KB.
// ===========================================================================
#define QOFF  0
#define KHOFF 8192
#define KLOFF 16384
#define VTOFF 24576
#define POFF  32768
#define SMEM_ATT (40960 * 4)

__global__ void __launch_bounds__(256, 1) k_attn()
{
    extern __shared__ uint32_t smw[];
    const int tid = threadIdx.x;
    const int wid = tid >> 5, lane = tid & 31;
    const int wm = wid >> 2, wn = wid & 3;
    const int g = lane >> 2, t = lane & 3;
    const uint32_t xr = (uint32_t)((g & 6) << 1);
    const uint32_t sbase = smem_u32(smw);
    const size_t z = blockIdx.y;
    const int q0 = blockIdx.x * 128;

    const __half* Qg  = g_XMh + (z * Nn + q0) * (size_t)Dd;
    const __half* Khg = g_Xh  + z * (size_t)Nn * Dd;
    const __half* Klg = g_Xl  + z * (size_t)Nn * Dd;
    const __half* VTg = g_VTh + z * (size_t)Dd * Nn;

    auto load_tile = [&](uint32_t woff, const __half* src, int st) {
        #pragma unroll
        for (int i = 0; i < 8; ++i) {
            int idx = tid + (i << 8);
            int r = idx >> 4, ch = idx & 15;
            int kc = ch >> 2, c2 = ch & 3;
            uint32_t d = sbase + woff * 4
                       + (uint32_t)(kc * 8192 + r * 64 + ((c2 ^ ((r >> 1) & 3)) << 4));
            cp16(d, src + (size_t)r * st + kc * 32 + c2 * 8);
        }
    };

    float oacc[4][4][4];
    float rsum[4][2];
    #pragma unroll
    for (int a = 0; a < 4; ++a) {
        rsum[a][0] = 0.f; rsum[a][1] = 0.f;
        #pragma unroll
        for (int b = 0; b < 4; ++b)
            #pragma unroll
            for (int c = 0; c < 4; ++c) oacc[a][b][c] = 0.f;
    }

    load_tile(QOFF,  Qg,  Dd);
    load_tile(KHOFF, Khg, Dd);
    load_tile(KLOFF, Klg, Dd);
    load_tile(VTOFF, VTg, Nn);
    CP_COMMIT();
    CP_WAIT0();
    __syncthreads();

    for (int kt = 0; kt < 8; ++kt) {
        if (kt > 0) { CP_WAIT1(); __syncthreads(); }   // K(kt) ready

        // ---- S = Q @ K^T (2-term over B) ----
        float sacc[4][4][4];
        #pragma unroll
        for (int a = 0; a < 4; ++a)
            #pragma unroll
            for (int b = 0; b < 4; ++b)
                #pragma unroll
                for (int c = 0; c < 4; ++c) sacc[a][b][c] = 0.f;

        #pragma unroll
        for (int kc = 0; kc < 4; ++kc) {
            const uint32_t* AH = smw + QOFF  + kc * 2048;
            const uint32_t* BH = smw + KHOFF + kc * 2048;
            const uint32_t* BL = smw + KLOFF + kc * 2048;
            #pragma unroll
            for (int ks = 0; ks < 2; ++ks) {
                const uint32_t w0 = (uint32_t)(ks * 8 + t) ^ xr;
                const uint32_t w1 = (uint32_t)(ks * 8 + t + 4) ^ xr;
                uint32_t ah[4][4], bb[4][2];
                #pragma unroll
                for (int mf = 0; mf < 4; ++mf) {
                    int R0 = (wm * 64 + mf * 16 + g) * 16, R1 = R0 + 128;
                    ah[mf][0] = AH[R0 + w0];
                    ah[mf][1] = AH[R1 + w0];
                    ah[mf][2] = AH[R0 + w1];
                    ah[mf][3] = AH[R1 + w1];
                }
                #pragma unroll
                for (int nf = 0; nf < 4; ++nf) {
                    int Rn = (wn * 32 + nf * 8 + g) * 16;
                    bb[nf][0] = BH[Rn + w0];
                    bb[nf][1] = BH[Rn + w1];
                }
                #pragma unroll
                for (int mf = 0; mf < 4; ++mf)
                    #pragma unroll
                    for (int nf = 0; nf < 4; ++nf)
                        MMA_F16(sacc[mf][nf], ah[mf], bb[nf]);
                #pragma unroll
                for (int nf = 0; nf < 4; ++nf) {
                    int Rn = (wn * 32 + nf * 8 + g) * 16;
                    bb[nf][0] = BL[Rn + w0];
                    bb[nf][1] = BL[Rn + w1];
                }
                #pragma unroll
                for (int mf = 0; mf < 4; ++mf)
                    #pragma unroll
                    for (int nf = 0; nf < 4; ++nf)
                        MMA_F16(sacc[mf][nf], ah[mf], bb[nf]);
            }
        }

        // ---- P = exp(S - 12) -> fp16 smem, l partials ----
        #pragma unroll
        for (int mf = 0; mf < 4; ++mf)
            #pragma unroll
            for (int hh = 0; hh < 2; ++hh) {
                int r = wm * 64 + mf * 16 + g + 8 * hh;
                #pragma unroll
                for (int nf = 0; nf < 4; ++nf) {
                    float e0 = __expf(sacc[mf][nf][2*hh+0] - PSHIFT);
                    float e1 = __expf(sacc[mf][nf][2*hh+1] - PSHIFT);
                    __half p0 = __float2half_rn(e0), p1 = __float2half_rn(e1);
                    rsum[mf][hh] += __half2float(p0) + __half2float(p1);
                    __half2 pk = __halves2half2(p0, p1);
                    uint32_t w = (uint32_t)(POFF + wn * 2048 + r * 16
                               + ((nf ^ ((r >> 1) & 3)) << 2) + t);
                    smw[w] = *(uint32_t*)&pk;
                }
            }
        __syncthreads();
        if (kt < 7) {
            load_tile(KHOFF, Khg + (size_t)(kt + 1) * 128 * Dd, Dd);
            load_tile(KLOFF, Klg + (size_t)(kt + 1) * 128 * Dd, Dd);
            CP_COMMIT();
            CP_WAIT1();                               // VT(kt) ready
        } else {
            CP_WAIT0();
        }
        __syncthreads();

        // ---- O += P @ VT ----
        #pragma unroll
        for (int kc = 0; kc < 4; ++kc) {
            const uint32_t* AH = smw + POFF  + kc * 2048;
            const uint32_t* BH = smw + VTOFF + kc * 2048;
            #pragma unroll
            for (int ks = 0; ks < 2; ++ks) {
                const uint32_t w0 = (uint32_t)(ks * 8 + t) ^ xr;
                const uint32_t w1 = (uint32_t)(ks * 8 + t + 4) ^ xr;
                uint32_t ah[4][4], bb[4][2];
                #pragma unroll
                for (int mf = 0; mf < 4; ++mf) {
                    int R0 = (wm * 64 + mf * 16 + g) * 16, R1 = R0 + 128;
                    ah[mf][0] = AH[R0 + w0];
                    ah[mf][1] = AH[R1 + w0];
                    ah[mf][2] = AH[R0 + w1];
                    ah[mf][3] = AH[R1 + w1];
                }
                #pragma unroll
                for (int nf = 0; nf < 4; ++nf) {
                    int Rn = (wn * 32 + nf * 8 + g) * 16;
                    bb[nf][0] = BH[Rn + w0];
                    bb[nf][1] = BH[Rn + w1];
                }
                #pragma unroll
                for (int mf = 0; mf < 4; ++mf)
                    #pragma unroll
                    for (int nf = 0; nf < 4; ++nf)
                        MMA_F16(oacc[mf][nf], ah[mf], bb[nf]);
            }
        }
        __syncthreads();
        if (kt < 7) {
            load_tile(VTOFF, VTg + (kt + 1) * 128, Nn);
            CP_COMMIT();
        }
    }

    // ---- final: reduce l, normalize, store ----
    float* ssum = (float*)(smw + POFF);
    #pragma unroll
    for (int mf = 0; mf < 4; ++mf)
        #pragma unroll
        for (int hh = 0; hh < 2; ++hh) {
            float s = rsum[mf][hh];
            s += __shfl_xor_sync(0xffffffffu, s, 1);
            s += __shfl_xor_sync(0xffffffffu, s, 2);
            if (t == 0)
                ssum[(wm * 64 + mf * 16 + g + 8 * hh) * 4 + wn] = s;
        }
    __syncthreads();
    #pragma unroll
    for (int mf = 0; mf < 4; ++mf)
        #pragma unroll
        for (int hh = 0; hh < 2; ++hh) {
            int r = wm * 64 + mf * 16 + g + 8 * hh;
            const float* lp = ssum + r * 4;
            float inv = 1.f / ((lp[0] + lp[1]) + (lp[2] + lp[3]));
            float* dst = g_O + (z * Nn + q0 + r) * (size_t)Dd;
            #pragma unroll
            for (int nf = 0; nf < 4; ++nf) {
                int col = wn * 32 + nf * 8 + 2 * t;
                *(float2*)(dst + col) =
                    make_float2(oacc[mf][nf][2*hh+0] * inv,
                                oacc[mf][nf][2*hh+1] * inv);
            }
        }
}

// ---------------------------------------------------------------------------
// Transpose X_hi -> VT_hi  ([z][n][d] -> [z][d][n])
// ---------------------------------------------------------------------------
__global__ void __launch_bounds__(256) k_transpose()
{
    __shared__ __half th[32][33];
    const int z  = blockIdx.z;
    const int d0 = blockIdx.y << 5;
    const int nb = blockIdx.x << 5;
    const int lx = threadIdx.x, ly = threadIdx.y;
    const __half* sh = g_Xh + (size_t)z * Nn * Dd;
    #pragma unroll
    for (int i = 0; i < 32; i += 8)
        th[ly + i][lx] = sh[(size_t)(nb + ly + i) * Dd + d0 + lx];
    __syncthreads();
    __half* dh = g_VTh + (size_t)z * Dd * Nn;
    #pragma unroll
    for (int i = 0; i < 32; i += 8)
        dh[(size_t)(d0 + ly + i) * Nn + nb + lx] = th[lx][ly + i];
}

// ---------------------------------------------------------------------------
// LayerNorm + exact GELU over c (gather heads)
// ---------------------------------------------------------------------------
__global__ void __launch_bounds__(256) k_ln_gelu(const float* __restrict__ gamma,
                                                 const float* __restrict__ beta,
                                                 float* __restrict__ out)
{
    const int row = blockIdx.x;
    const int bbi = row >> 10, nn = row & 1023;
    const int tid = threadIdx.x;
    const int c0 = tid * 4, head = c0 >> 7, dd = c0 & 127;

    const float* src = g_O + (((size_t)bbi * Hh + head) * Nn + nn) * Dd + dd;
    float4 v = *(const float4*)src;

    float s = v.x + v.y + v.z + v.w;
    float q = v.x*v.x + v.y*v.y + v.z*v.z + v.w*v.w;
    #pragma unroll
    for (int off = 16; off >= 1; off >>= 1) {
        s += __shfl_xor_sync(0xffffffffu, s, off);
        q += __shfl_xor_sync(0xffffffffu, q, off);
    }
    __shared__ float ss[8], sq[8];
    if ((tid & 31) == 0) { ss[tid >> 5] = s; sq[tid >> 5] = q; }
    __syncthreads();
    float st = 0.f, qt = 0.f;
    #pragma unroll
    for (int k = 0; k < 8; ++k) { st += ss[k]; qt += sq[k]; }

    const float mean = st * (1.f / (float)Cc);
    const float var  = qt * (1.f / (float)Cc) - mean * mean;
    const float rstd = rsqrtf(var + 1e-5f);

    float4 gm = *(const float4*)(gamma + c0);
    float4 be = *(const float4*)(beta + c0);
    float y0 = (v.x - mean) * rstd * gm.x + be.x;
    float y1 = (v.y - mean) * rstd * gm.y + be.y;
    float y2 = (v.z - mean) * rstd * gm.z + be.z;
    float y3 = (v.w - mean) * rstd * gm.w + be.w;

    const float k2 = 0.70710678118654752440f;
    float4 rr;
    rr.x = 0.5f * y0 * (1.f + erff(y0 * k2));
    rr.y = 0.5f * y1 * (1.f + erff(y1 * k2));
    rr.z = 0.5f * y2 * (1.f + erff(y2 * k2));
    rr.w = 0.5f * y3 * (1.f + erff(y3 * k2));
    *(float4*)(out + (size_t)row * Cc + c0) = rr;
}

// ---------------------------------------------------------------------------
#define SMEM_M0 (3 * 6144 * 4)    // 73728 B  (mode 0, 2-term)
#define SMEM_M1 (3 * 8192 * 4)    // 98304 B  (mode 1, 3-term)

extern "C" void kernel_launch(void* const* d_in, const int* in_sizes, int n_in,
                              void* d_out, int out_size)
{
    const float* h     = (const float*)d_in[0];
    const float* W_w   = (const float*)d_in[1];
    const float* W_b   = (const float*)d_in[2];
    const float* Mmat  = (const float*)d_in[3];
    const float* gamma = (const float*)d_in[4];
    const float* beta  = (const float*)d_in[5];
    float* out = (float*)d_out;

    cudaFuncSetAttribute(k_gemm<0>, cudaFuncAttributeMaxDynamicSharedMemorySize, SMEM_M0);
    cudaFuncSetAttribute(k_gemm<1>, cudaFuncAttributeMaxDynamicSharedMemorySize, SMEM_M1);
    cudaFuncSetAttribute(k_attn,    cudaFuncAttributeMaxDynamicSharedMemorySize, SMEM_ATT);

    __half *hh, *hl, *wh;
    cudaGetSymbolAddress((void**)&hh, g_hh);
    cudaGetSymbolAddress((void**)&hl, g_hl);
    cudaGetSymbolAddress((void**)&wh, g_Wh);

    // 0) pre-split inputs (W: hi only)
    k_split<<<(MROWS * Cc / 4) / 256, 256>>>(h,   hh, hl, MROWS * Cc / 4);
    k_split<<<(Cc * Cc / 4) / 256,    256>>>(W_w, wh, nullptr, Cc * Cc / 4);
    k_splitMt<<<1, 256>>>(Mmat);

    // 1) X = h @ W^T + b          -> X_hi/X_lo          (2-term f16)
    k_gemm<0><<<dim3(Hh, MROWS / 128), 128, SMEM_M0>>>(W_b);
    // 2) X^T (hi only)            -> VT_hi
    k_transpose<<<dim3(Nn / 32, Dd / 32, BHn), dim3(32, 8)>>>();
    // 3) XM = X @ M               -> XM_hi               (3-term f16)
    k_gemm<1><<<dim3((BHn * Nn) / 128), 128, SMEM_M1>>>(nullptr);
    // 4+5) fused attention        -> g_O
    k_attn<<<dim3(Nn / 128, BHn), 256, SMEM_ATT>>>();
    // 6) LayerNorm + GELU         -> out
    k_ln_gelu<<<MROWS, 256>>>(gamma, beta, out);
}